// round 3
// baseline (speedup 1.0000x reference)
#include <cuda_runtime.h>
#include <math.h>
#include <stdint.h>

// ---------------- problem constants ----------------
#define Bc   2
#define Tc   16
#define Lc   256
#define Mc   512
#define Dc   1024
#define Hc   16
#define DHc  64
#define HTc  8
#define ROTc 32
#define TLc  4096            // T*L
#define NR   8192            // B*T*L rows
#define SCALEF 0.125f        // 1/sqrt(64)
#define NEGF  (-1000000000.0f)

// ---------------- scratch (device globals; no allocs allowed) ----------------
__device__ float g_buf1[(size_t)NR * Dc];        // xn / xn2 / xn3
__device__ float g_cn  [(size_t)Bc * Mc * Dc];   // LN(context)
__device__ float g_q   [(size_t)NR * Dc];        // cross-attn Q
__device__ float g_kv  [(size_t)Bc * Mc * 2048]; // cross-attn K|V
__device__ float g_oc  [(size_t)NR * Dc];        // cross-attn out, reused as temporal out (N x 512)
__device__ float g_x1  [(size_t)NR * Dc];
__device__ float g_qkv [(size_t)NR * 1536];
__device__ float g_x2  [(size_t)NR * Dc];
__device__ float g_h   [(size_t)NR * 4096];

// ---------------- LayerNorm: one block per row, D=1024 ----------------
__global__ void ln_kernel(const float* __restrict__ x, const float* __restrict__ g,
                          const float* __restrict__ b, float* __restrict__ y) {
    const int row = blockIdx.x;
    const int tid = threadIdx.x;                 // 256 threads
    const float4* xr = (const float4*)(x + (size_t)row * Dc);
    float4 v = xr[tid];
    float s  = v.x + v.y + v.z + v.w;
    float ss = v.x*v.x + v.y*v.y + v.z*v.z + v.w*v.w;

    __shared__ float rs[8], rss[8];
    for (int o = 16; o > 0; o >>= 1) {
        s  += __shfl_down_sync(0xffffffff, s,  o);
        ss += __shfl_down_sync(0xffffffff, ss, o);
    }
    const int wid = tid >> 5, lane = tid & 31;
    if (lane == 0) { rs[wid] = s; rss[wid] = ss; }
    __syncthreads();
    if (tid == 0) {
        float ts = 0.f, tss = 0.f;
        #pragma unroll
        for (int i = 0; i < 8; i++) { ts += rs[i]; tss += rss[i]; }
        rs[0] = ts; rss[0] = tss;
    }
    __syncthreads();
    const float mean = rs[0] * (1.0f / Dc);
    const float var  = rss[0] * (1.0f / Dc) - mean * mean;
    const float inv  = rsqrtf(var + 1e-5f);

    float4 gg = ((const float4*)g)[tid];
    float4 bb = ((const float4*)b)[tid];
    float4 o;
    o.x = (v.x - mean) * inv * gg.x + bb.x;
    o.y = (v.y - mean) * inv * gg.y + bb.y;
    o.z = (v.z - mean) * inv * gg.z + bb.z;
    o.w = (v.w - mean) * inv * gg.w + bb.w;
    ((float4*)(y + (size_t)row * Dc))[tid] = o;
}

// ---------------- SGEMM 128x128 tile, BK=8, 256 threads, 8x8/thread, double-buffered ----
// C[N,M] = A[N,K] @ B[K,M] (+bias[M]) (gelu) (+res[N,M])
// Requirements: N % 128 == 0, M % 128 == 0, K % 8 == 0 (all shapes here comply).
template<int BIAS, int RES, int GELU>
__global__ void __launch_bounds__(256)
sgemm_kernel(const float* __restrict__ A, const float* __restrict__ Bm,
             const float* __restrict__ bias, const float* __restrict__ res,
             float* __restrict__ C, int Nn, int K, int Mm) {
    __shared__ float As[2][8][132];   // A transposed: As[k][m], padded
    __shared__ float Bs[2][8][132];   // Bs[k][n], padded

    const int tid  = threadIdx.x;
    const int row0 = blockIdx.y * 128;
    const int col0 = blockIdx.x * 128;
    const int tx = tid & 15;          // 0..15 -> 8 cols each
    const int ty = tid >> 4;          // 0..15 -> 8 rows each

    // A-tile load mapping: 128 rows x 8 cols, one float4 per thread
    const int ar = tid >> 1;          // 0..127
    const int ac = (tid & 1) * 4;     // 0 or 4
    // B-tile load mapping: 8 rows x 128 cols, one float4 per thread
    const int br = tid >> 5;          // 0..7
    const int bc = (tid & 31) * 4;    // 0..124

    const float* Aptr = A + (size_t)(row0 + ar) * K + ac;
    const float* Bptr = Bm + (size_t)br * Mm + col0 + bc;

    // preload stage 0
    float4 av = *(const float4*)Aptr;
    float4 bv = *(const float4*)Bptr;
    As[0][ac + 0][ar] = av.x;
    As[0][ac + 1][ar] = av.y;
    As[0][ac + 2][ar] = av.z;
    As[0][ac + 3][ar] = av.w;
    *(float4*)&Bs[0][br][bc] = bv;
    __syncthreads();

    float acc[8][8] = {};
    int buf = 0;
    for (int k0 = 0; k0 < K; k0 += 8) {
        const bool more = (k0 + 8) < K;
        if (more) {
            av = *(const float4*)(Aptr + k0 + 8);
            bv = *(const float4*)(Bptr + (size_t)(k0 + 8) * Mm);
        }
        #pragma unroll
        for (int kk = 0; kk < 8; kk++) {
            float4 a0 = *(const float4*)&As[buf][kk][ty * 8];
            float4 a1 = *(const float4*)&As[buf][kk][ty * 8 + 4];
            float4 b0 = *(const float4*)&Bs[buf][kk][tx * 8];
            float4 b1 = *(const float4*)&Bs[buf][kk][tx * 8 + 4];
            float aa[8] = {a0.x, a0.y, a0.z, a0.w, a1.x, a1.y, a1.z, a1.w};
            float bb[8] = {b0.x, b0.y, b0.z, b0.w, b1.x, b1.y, b1.z, b1.w};
            #pragma unroll
            for (int i = 0; i < 8; i++)
                #pragma unroll
                for (int j = 0; j < 8; j++)
                    acc[i][j] += aa[i] * bb[j];
        }
        if (more) {
            buf ^= 1;
            As[buf][ac + 0][ar] = av.x;
            As[buf][ac + 1][ar] = av.y;
            As[buf][ac + 2][ar] = av.z;
            As[buf][ac + 3][ar] = av.w;
            *(float4*)&Bs[buf][br][bc] = bv;
            __syncthreads();
        }
    }

    // epilogue
    #pragma unroll
    for (int i = 0; i < 8; i++) {
        const int r = row0 + ty * 8 + i;
        #pragma unroll
        for (int j4 = 0; j4 < 8; j4 += 4) {
            const int c = col0 + tx * 8 + j4;
            float4 v = make_float4(acc[i][j4], acc[i][j4+1], acc[i][j4+2], acc[i][j4+3]);
            if (BIAS) {
                float4 bb = *(const float4*)(bias + c);
                v.x += bb.x; v.y += bb.y; v.z += bb.z; v.w += bb.w;
            }
            if (GELU) {
                v.x = 0.5f * v.x * (1.0f + erff(v.x * 0.70710678118654752f));
                v.y = 0.5f * v.y * (1.0f + erff(v.y * 0.70710678118654752f));
                v.z = 0.5f * v.z * (1.0f + erff(v.z * 0.70710678118654752f));
                v.w = 0.5f * v.w * (1.0f + erff(v.w * 0.70710678118654752f));
            }
            if (RES) {
                float4 rr = *(const float4*)(res + (size_t)r * Mm + c);
                v.x += rr.x; v.y += rr.y; v.z += rr.z; v.w += rr.w;
            }
            *(float4*)(C + (size_t)r * Mm + c) = v;
        }
    }
}

// ---------------- cross attention: block per (b,h,q-row) ----------------
__global__ void __launch_bounds__(256)
cross_attn_kernel(const float* __restrict__ q, const float* __restrict__ kv,
                  const int* __restrict__ cmask, float* __restrict__ o) {
    const int n = blockIdx.x;     // 0..4095
    const int h = blockIdx.y;     // 0..15
    const int b = blockIdx.z;     // 0..1
    const int tid = threadIdx.x;  // 256

    __shared__ float qs[64];
    __shared__ float p[Mc];
    __shared__ float red[256];

    const float* qrow = q + ((size_t)(b * TLc + n)) * 1024 + h * 64;
    if (tid < 64) qs[tid] = qrow[tid];
    __syncthreads();

    // scores
    #pragma unroll
    for (int m = tid; m < Mc; m += 256) {
        float s;
        if (cmask[b * Mc + m]) {
            const float* kr = kv + ((size_t)(b * Mc + m)) * 2048 + h * 64;
            float acc = 0.f;
            #pragma unroll
            for (int d = 0; d < 64; d += 4) {
                float4 kk = *(const float4*)(kr + d);
                acc += qs[d] * kk.x + qs[d + 1] * kk.y + qs[d + 2] * kk.z + qs[d + 3] * kk.w;
            }
            s = acc * SCALEF;
        } else {
            s = NEGF;
        }
        p[m] = s;
    }
    __syncthreads();

    // max
    red[tid] = fmaxf(p[tid], p[tid + 256]);
    __syncthreads();
    for (int st = 128; st > 0; st >>= 1) {
        if (tid < st) red[tid] = fmaxf(red[tid], red[tid + st]);
        __syncthreads();
    }
    const float mx = red[0];
    __syncthreads();

    // exp + sum
    float lsum = 0.f;
    #pragma unroll
    for (int m = tid; m < Mc; m += 256) {
        float e = __expf(p[m] - mx);
        p[m] = e;
        lsum += e;
    }
    red[tid] = lsum;
    __syncthreads();
    for (int st = 128; st > 0; st >>= 1) {
        if (tid < st) red[tid] += red[tid + st];
        __syncthreads();
    }
    const float inv = 1.0f / red[0];
    __syncthreads();

    // P @ V : thread = (part 0..3, d 0..63)
    const int d = tid & 63, part = tid >> 6;
    const float* vb = kv + ((size_t)b * Mc) * 2048 + 1024 + h * 64 + d;
    float acc = 0.f;
    const int m0 = part * 128;
    #pragma unroll 8
    for (int m = m0; m < m0 + 128; m++) acc += p[m] * vb[(size_t)m * 2048];
    red[tid] = acc;
    __syncthreads();
    if (tid < 64) {
        float v = (red[tid] + red[tid + 64] + red[tid + 128] + red[tid + 192]) * inv;
        o[((size_t)(b * TLc + n)) * 1024 + h * 64 + tid] = v;
    }
}

// ---------------- temporal attention (+RoPE): block per (b,l,h) ----------------
__global__ void __launch_bounds__(128)
temporal_attn_kernel(const float* __restrict__ qkv, const float* __restrict__ rope,
                     const int* __restrict__ amask, float* __restrict__ ot) {
    const int l = blockIdx.x;     // 0..255
    const int h = blockIdx.y;     // 0..7
    const int b = blockIdx.z;     // 0..1
    const int tid = threadIdx.x;  // 128

    __shared__ float qs[16][64], ks[16][64], vs[16][64];
    __shared__ float ss[16][17];

    for (int idx = tid; idx < 1024; idx += 128) {
        const int t = idx >> 6, d = idx & 63;
        const size_t base = ((size_t)((b * Tc + t) * Lc + l)) * 1536 + h * 64 + d;
        qs[t][d] = qkv[base];
        ks[t][d] = qkv[base + 512];
        vs[t][d] = qkv[base + 1024];
    }
    __syncthreads();

    // RoPE on first 32 dims of q,k (pairs r, r+16)
    for (int idx = tid; idx < 256; idx += 128) {
        const int t = idx >> 4, r = idx & 15;
        const float p0 = rope[t * ROTc + r];
        const float p1 = rope[t * ROTc + r + 16];
        const float c0 = cosf(p0), s0 = sinf(p0);
        const float c1 = cosf(p1), s1 = sinf(p1);
        float a = qs[t][r], bb = qs[t][r + 16];
        qs[t][r]      = a * c0 - bb * s0;
        qs[t][r + 16] = bb * c1 + a * s1;
        a = ks[t][r]; bb = ks[t][r + 16];
        ks[t][r]      = a * c0 - bb * s0;
        ks[t][r + 16] = bb * c1 + a * s1;
    }
    __syncthreads();

    // scores 16x16
    for (int idx = tid; idx < 256; idx += 128) {
        const int tq = idx >> 4, tk = idx & 15;
        float acc = 0.f;
        #pragma unroll
        for (int d = 0; d < 64; d++) acc += qs[tq][d] * ks[tk][d];
        ss[tq][tk] = amask[b * Tc + tk] ? acc * SCALEF : NEGF;
    }
    __syncthreads();

    // softmax per query row
    if (tid < 16) {
        float mx = -1e30f;
        #pragma unroll
        for (int tk = 0; tk < 16; tk++) mx = fmaxf(mx, ss[tid][tk]);
        float sum = 0.f;
        #pragma unroll
        for (int tk = 0; tk < 16; tk++) { float e = __expf(ss[tid][tk] - mx); ss[tid][tk] = e; sum += e; }
        const float inv = 1.0f / sum;
        #pragma unroll
        for (int tk = 0; tk < 16; tk++) ss[tid][tk] *= inv;
    }
    __syncthreads();

    // P @ V, query-mask, write (N x 512) layout
    for (int idx = tid; idx < 1024; idx += 128) {
        const int tq = idx >> 6, d = idx & 63;
        float acc = 0.f;
        #pragma unroll
        for (int tk = 0; tk < 16; tk++) acc += ss[tq][tk] * vs[tk][d];
        const float qm = amask[b * Tc + tq] ? 1.0f : 0.0f;
        ot[((size_t)((b * Tc + tq) * Lc + l)) * 512 + h * 64 + d] = acc * qm;
    }
}

// ---------------- launcher ----------------
extern "C" void kernel_launch(void* const* d_in, const int* in_sizes, int n_in,
                              void* d_out, int out_size) {
    const float* x        = (const float*)d_in[0];
    const float* context  = (const float*)d_in[1];
    const float* rope     = (const float*)d_in[2];
    const float* ca_ng    = (const float*)d_in[3];
    const float* ca_nb    = (const float*)d_in[4];
    const float* ca_cng   = (const float*)d_in[5];
    const float* ca_cnb   = (const float*)d_in[6];
    const float* ca_wq    = (const float*)d_in[7];
    const float* ca_wkv   = (const float*)d_in[8];
    const float* ca_wo    = (const float*)d_in[9];
    const float* ta_ng    = (const float*)d_in[10];
    const float* ta_nb    = (const float*)d_in[11];
    const float* ta_wqkv  = (const float*)d_in[12];
    const float* ta_bqkv  = (const float*)d_in[13];
    const float* ta_wo    = (const float*)d_in[14];
    const float* ff_ng    = (const float*)d_in[15];
    const float* ff_nb    = (const float*)d_in[16];
    const float* ff_w1    = (const float*)d_in[17];
    const float* ff_w2    = (const float*)d_in[18];
    const int*   cmask    = (const int*)d_in[19];
    const int*   amask    = (const int*)d_in[20];
    float* out = (float*)d_out;

    float *buf1, *cn, *qb, *kvb, *oc, *x1, *qkvb, *x2, *hb;
    cudaGetSymbolAddress((void**)&buf1, g_buf1);
    cudaGetSymbolAddress((void**)&cn,   g_cn);
    cudaGetSymbolAddress((void**)&qb,   g_q);
    cudaGetSymbolAddress((void**)&kvb,  g_kv);
    cudaGetSymbolAddress((void**)&oc,   g_oc);
    cudaGetSymbolAddress((void**)&x1,   g_x1);
    cudaGetSymbolAddress((void**)&qkvb, g_qkv);
    cudaGetSymbolAddress((void**)&x2,   g_x2);
    cudaGetSymbolAddress((void**)&hb,   g_h);

    // 1) xn = LN(x); cn = LN(context)
    ln_kernel<<<NR, 256>>>(x, ca_ng, ca_nb, buf1);
    ln_kernel<<<Bc * Mc, 256>>>(context, ca_cng, ca_cnb, cn);

    // 2) q = xn @ ca_wq ; kv = cn @ ca_wkv
    sgemm_kernel<0,0,0><<<dim3(1024/128, NR/128), 256>>>(buf1, ca_wq, nullptr, nullptr, qb, NR, 1024, 1024);
    sgemm_kernel<0,0,0><<<dim3(2048/128, (Bc*Mc)/128), 256>>>(cn, ca_wkv, nullptr, nullptr, kvb, Bc*Mc, 1024, 2048);

    // 3) cross attention
    cross_attn_kernel<<<dim3(TLc, Hc, Bc), 256>>>(qb, kvb, cmask, oc);

    // 4) x1 = x + o @ ca_wo
    sgemm_kernel<0,1,0><<<dim3(1024/128, NR/128), 256>>>(oc, ca_wo, nullptr, x, x1, NR, 1024, 1024);

    // 5) xn2 = LN(x1); qkv = xn2 @ ta_wqkv + bias
    ln_kernel<<<NR, 256>>>(x1, ta_ng, ta_nb, buf1);
    sgemm_kernel<1,0,0><<<dim3(1536/128, NR/128), 256>>>(buf1, ta_wqkv, ta_bqkv, nullptr, qkvb, NR, 1024, 1536);

    // 6) temporal attention (RoPE fused) -> oc reused as (N x 512)
    temporal_attn_kernel<<<dim3(Lc, HTc, Bc), 128>>>(qkvb, rope, amask, oc);

    // 7) x2 = x1 + ot @ ta_wo
    sgemm_kernel<0,1,0><<<dim3(1024/128, NR/128), 256>>>(oc, ta_wo, nullptr, x1, x2, NR, 512, 1024);

    // 8) xn3 = LN(x2); h = gelu(xn3 @ ff_w1); out = x2 + h @ ff_w2
    ln_kernel<<<NR, 256>>>(x2, ff_ng, ff_nb, buf1);
    sgemm_kernel<0,0,1><<<dim3(4096/128, NR/128), 256>>>(buf1, ff_w1, nullptr, nullptr, hb, NR, 1024, 4096);
    sgemm_kernel<0,1,0><<<dim3(1024/128, NR/128), 256>>>(hb, ff_w2, nullptr, x2, out, NR, 4096, 1024);
}

// round 4
// speedup vs baseline: 1.6338x; 1.6338x over previous
#include <cuda_runtime.h>
#include <cuda_bf16.h>
#include <math.h>
#include <stdint.h>

// ---------------- problem constants ----------------
#define Bc   2
#define Tc   16
#define Lc   256
#define Mc   512
#define Dc   1024
#define Hc   16
#define DHc  64
#define HTc  8
#define ROTc 32
#define TLc  4096            // T*L
#define NR   8192            // B*T*L rows
#define SCALEF 0.125f        // 1/sqrt(64)
#define NEGF  (-1000000000.0f)

// ---------------- scratch (device globals; no allocs allowed) ----------------
// bf16 split activation buffers
__device__ __nv_bfloat16 g_xnh[(size_t)NR * Dc];
__device__ __nv_bfloat16 g_xnl[(size_t)NR * Dc];
__device__ __nv_bfloat16 g_cnh[(size_t)1024 * Dc];
__device__ __nv_bfloat16 g_cnl[(size_t)1024 * Dc];
__device__ __nv_bfloat16 g_och[(size_t)NR * Dc];   // cross out (Nx1024), reused temporal (Nx512)
__device__ __nv_bfloat16 g_ocl[(size_t)NR * Dc];
__device__ __nv_bfloat16 g_hh [(size_t)NR * 4096];
__device__ __nv_bfloat16 g_hl [(size_t)NR * 4096];
// bf16 split weights (concatenated)
#define WQ_OFF    0
#define WKV_OFF   1048576
#define WO_OFF    3145728
#define WQKV_OFF  4194304
#define TAWO_OFF  5767168
#define FFW1_OFF  6291456
#define FFW2_OFF  10485760
#define WTOTAL    14680064
__device__ __nv_bfloat16 g_wh[WTOTAL];
__device__ __nv_bfloat16 g_wl[WTOTAL];
// fp32 buffers
__device__ float g_q  [(size_t)NR * Dc];
__device__ float g_kv [(size_t)1024 * 2048];
__device__ float g_qkv[(size_t)NR * 1536];
__device__ float g_x1 [(size_t)NR * Dc];
__device__ float g_x2 [(size_t)NR * Dc];

// ---------------- helpers ----------------
__device__ __forceinline__ void split_val(float v, __nv_bfloat16& hi, __nv_bfloat16& lo) {
    hi = __float2bfloat16_rn(v);
    lo = __float2bfloat16_rn(v - __bfloat162float(hi));
}

__device__ __forceinline__ void ldsm_x4(uint32_t* r, uint32_t addr) {
    asm volatile("ldmatrix.sync.aligned.m8n8.x4.shared.b16 {%0,%1,%2,%3}, [%4];"
        : "=r"(r[0]), "=r"(r[1]), "=r"(r[2]), "=r"(r[3]) : "r"(addr));
}
__device__ __forceinline__ void ldsm_x4_t(uint32_t* r, uint32_t addr) {
    asm volatile("ldmatrix.sync.aligned.m8n8.x4.trans.shared.b16 {%0,%1,%2,%3}, [%4];"
        : "=r"(r[0]), "=r"(r[1]), "=r"(r[2]), "=r"(r[3]) : "r"(addr));
}
__device__ __forceinline__ void mma_bf16(float* c, const uint32_t* a, uint32_t b0, uint32_t b1) {
    asm volatile("mma.sync.aligned.m16n8k16.row.col.f32.bf16.bf16.f32 "
        "{%0,%1,%2,%3},{%4,%5,%6,%7},{%8,%9},{%0,%1,%2,%3};"
        : "+f"(c[0]), "+f"(c[1]), "+f"(c[2]), "+f"(c[3])
        : "r"(a[0]), "r"(a[1]), "r"(a[2]), "r"(a[3]), "r"(b0), "r"(b1));
}

// ---------------- weight split kernel ----------------
__global__ void split_kernel(const float* __restrict__ w, __nv_bfloat16* __restrict__ hi,
                             __nv_bfloat16* __restrict__ lo, int n) {
    int i = (blockIdx.x * blockDim.x + threadIdx.x) * 4;
    if (i >= n) return;
    float4 v = *(const float4*)(w + i);
    __nv_bfloat16 h0, h1, h2, h3, l0, l1, l2, l3;
    split_val(v.x, h0, l0); split_val(v.y, h1, l1);
    split_val(v.z, h2, l2); split_val(v.w, h3, l3);
    __nv_bfloat162 a, b;
    a.x = h0; a.y = h1; b.x = h2; b.y = h3;
    *(__nv_bfloat162*)(hi + i) = a; *(__nv_bfloat162*)(hi + i + 2) = b;
    a.x = l0; a.y = l1; b.x = l2; b.y = l3;
    *(__nv_bfloat162*)(lo + i) = a; *(__nv_bfloat162*)(lo + i + 2) = b;
}

// ---------------- LayerNorm: one block per row, D=1024, bf16 split out ------
__global__ void ln_kernel(const float* __restrict__ x, const float* __restrict__ g,
                          const float* __restrict__ b,
                          __nv_bfloat16* __restrict__ yh, __nv_bfloat16* __restrict__ yl) {
    const int row = blockIdx.x;
    const int tid = threadIdx.x;                 // 256 threads
    const float4* xr = (const float4*)(x + (size_t)row * Dc);
    float4 v = xr[tid];
    float s  = v.x + v.y + v.z + v.w;
    float ss = v.x*v.x + v.y*v.y + v.z*v.z + v.w*v.w;

    __shared__ float rs[8], rss[8];
    for (int o = 16; o > 0; o >>= 1) {
        s  += __shfl_down_sync(0xffffffff, s,  o);
        ss += __shfl_down_sync(0xffffffff, ss, o);
    }
    const int wid = tid >> 5, lane = tid & 31;
    if (lane == 0) { rs[wid] = s; rss[wid] = ss; }
    __syncthreads();
    if (tid == 0) {
        float ts = 0.f, tss = 0.f;
        #pragma unroll
        for (int i = 0; i < 8; i++) { ts += rs[i]; tss += rss[i]; }
        rs[0] = ts; rss[0] = tss;
    }
    __syncthreads();
    const float mean = rs[0] * (1.0f / Dc);
    const float var  = rss[0] * (1.0f / Dc) - mean * mean;
    const float inv  = rsqrtf(var + 1e-5f);

    float4 gg = ((const float4*)g)[tid];
    float4 bb = ((const float4*)b)[tid];
    float o0 = (v.x - mean) * inv * gg.x + bb.x;
    float o1 = (v.y - mean) * inv * gg.y + bb.y;
    float o2 = (v.z - mean) * inv * gg.z + bb.z;
    float o3 = (v.w - mean) * inv * gg.w + bb.w;
    __nv_bfloat16 h0,h1,h2,h3,l0,l1,l2,l3;
    split_val(o0,h0,l0); split_val(o1,h1,l1); split_val(o2,h2,l2); split_val(o3,h3,l3);
    size_t off = (size_t)row * Dc + tid * 4;
    __nv_bfloat162 p;
    p.x=h0; p.y=h1; *(__nv_bfloat162*)(yh+off)   = p;
    p.x=h2; p.y=h3; *(__nv_bfloat162*)(yh+off+2) = p;
    p.x=l0; p.y=l1; *(__nv_bfloat162*)(yl+off)   = p;
    p.x=l2; p.y=l3; *(__nv_bfloat162*)(yl+off+2) = p;
}

// ---------------- split-bf16 tensor-core GEMM -------------------------------
// C[N,M] = (Ahi+Alo)[N,K] @ (Bhi+Blo)[K,M]  (+bias) (gelu) (+res)
// 128x128 CTA tile, BK=16, 8 warps (2x4), warp tile 64x32, double-buffered.
// N%128==0, M%128==0, K%16==0.
#define ASTR 48      // bytes per A smem row (16 bf16 = 32B + 16B pad)
#define BSTR 272     // bytes per B smem row (128 bf16 = 256B + 16B pad)
#define ASZ  (128*ASTR)           // 6144 per (buf,arr)
#define BSZ  (16*BSTR)            // 4352 per (buf,arr)
#define SMEM_A_TOT (2*2*ASZ)      // 24576
#define SMEM_B_TOT (2*2*BSZ)      // 17408

template<int BIAS, int RES, int GELU, int OSPLIT>
__global__ void __launch_bounds__(256, 1)
bgemm_kernel(const __nv_bfloat16* __restrict__ Ahi, const __nv_bfloat16* __restrict__ Alo,
             const __nv_bfloat16* __restrict__ Bhi, const __nv_bfloat16* __restrict__ Blo,
             const float* __restrict__ bias, const float* __restrict__ res,
             float* __restrict__ C, __nv_bfloat16* __restrict__ Chi, __nv_bfloat16* __restrict__ Clo,
             int K, int Mm) {
    __shared__ __align__(16) unsigned char smem[SMEM_A_TOT + SMEM_B_TOT];

    const int tid  = threadIdx.x;
    const int lane = tid & 31, wid = tid >> 5;
    const int warp_m = wid & 1, warp_n = wid >> 1;   // 2 x 4
    const int row0 = blockIdx.y * 128, col0 = blockIdx.x * 128;

    // gmem tile load mapping
    const int a_m = tid >> 1, a_k = (tid & 1) * 8;   // 128 rows x 16 k
    const int b_k = tid >> 4, b_n = (tid & 15) * 8;  // 16 rows x 128 n
    const __nv_bfloat16* pAh = Ahi + (size_t)(row0 + a_m) * K + a_k;
    const __nv_bfloat16* pAl = Alo + (size_t)(row0 + a_m) * K + a_k;
    const __nv_bfloat16* pBh = Bhi + (size_t)b_k * Mm + col0 + b_n;
    const __nv_bfloat16* pBl = Blo + (size_t)b_k * Mm + col0 + b_n;
    const int sa = a_m * ASTR + a_k * 2;
    const int sb = b_k * BSTR + b_n * 2;

    // preload stage 0
    uint4 rah = *(const uint4*)pAh;
    uint4 ral = *(const uint4*)pAl;
    uint4 rbh = *(const uint4*)pBh;
    uint4 rbl = *(const uint4*)pBl;
    *(uint4*)(smem + 0*ASZ + sa) = rah;                 // buf0, hi
    *(uint4*)(smem + 1*ASZ + sa) = ral;                 // buf0, lo
    *(uint4*)(smem + SMEM_A_TOT + 0*BSZ + sb) = rbh;
    *(uint4*)(smem + SMEM_A_TOT + 1*BSZ + sb) = rbl;
    __syncthreads();

    float acc[4][4][4];
    #pragma unroll
    for (int i = 0; i < 4; i++)
        #pragma unroll
        for (int j = 0; j < 4; j++)
            #pragma unroll
            for (int k = 0; k < 4; k++) acc[i][j][k] = 0.f;

    const uint32_t sbase = (uint32_t)__cvta_generic_to_shared(smem);
    // ldmatrix lane address bases
    const uint32_t aAddr = sbase + (uint32_t)((warp_m*64 + (lane & 15)) * ASTR + (lane >> 4) * 16);
    const uint32_t bAddr = sbase + SMEM_A_TOT
                         + (uint32_t)((lane & 15) * BSTR + (warp_n*32 + (lane >> 4)*8) * 2);

    const int nsteps = K >> 4;
    for (int s = 0; s < nsteps; s++) {
        const int buf = s & 1;
        const bool more = (s + 1) < nsteps;
        if (more) {
            rah = *(const uint4*)(pAh + (size_t)(s+1) * 16);
            ral = *(const uint4*)(pAl + (size_t)(s+1) * 16);
            rbh = *(const uint4*)(pBh + (size_t)(s+1) * 16 * Mm);
            rbl = *(const uint4*)(pBl + (size_t)(s+1) * 16 * Mm);
        }

        // load fragments
        uint32_t ah[4][4], al[4][4], bh[2][4], bl[2][4];
        const uint32_t aoffH = (uint32_t)((buf*2 + 0) * ASZ);
        const uint32_t aoffL = (uint32_t)((buf*2 + 1) * ASZ);
        const uint32_t boffH = (uint32_t)((buf*2 + 0) * BSZ);
        const uint32_t boffL = (uint32_t)((buf*2 + 1) * BSZ);
        #pragma unroll
        for (int wm = 0; wm < 4; wm++) {
            ldsm_x4(ah[wm], aAddr + aoffH + wm * 16 * ASTR);
            ldsm_x4(al[wm], aAddr + aoffL + wm * 16 * ASTR);
        }
        #pragma unroll
        for (int bn = 0; bn < 2; bn++) {
            ldsm_x4_t(bh[bn], bAddr + boffH + bn * 32);
            ldsm_x4_t(bl[bn], bAddr + boffL + bn * 32);
        }

        // mma: hi*hi + hi*lo + lo*hi
        #pragma unroll
        for (int wm = 0; wm < 4; wm++) {
            #pragma unroll
            for (int bn = 0; bn < 2; bn++) {
                #pragma unroll
                for (int half = 0; half < 2; half++) {
                    float* c = acc[wm][bn*2 + half];
                    const uint32_t h0 = bh[bn][half*2], h1 = bh[bn][half*2+1];
                    const uint32_t l0 = bl[bn][half*2], l1 = bl[bn][half*2+1];
                    mma_bf16(c, ah[wm], h0, h1);
                    mma_bf16(c, ah[wm], l0, l1);
                    mma_bf16(c, al[wm], h0, h1);
                }
            }
        }

        if (more) {
            const int nb = buf ^ 1;
            *(uint4*)(smem + (nb*2 + 0)*ASZ + sa) = rah;
            *(uint4*)(smem + (nb*2 + 1)*ASZ + sa) = ral;
            *(uint4*)(smem + SMEM_A_TOT + (nb*2 + 0)*BSZ + sb) = rbh;
            *(uint4*)(smem + SMEM_A_TOT + (nb*2 + 1)*BSZ + sb) = rbl;
            __syncthreads();
        }
    }

    // epilogue
    const int gID = lane >> 2, tig = lane & 3;
    #pragma unroll
    for (int wm = 0; wm < 4; wm++) {
        const int r0 = row0 + warp_m*64 + wm*16 + gID;
        const int r1 = r0 + 8;
        #pragma unroll
        for (int n8 = 0; n8 < 4; n8++) {
            const int cc = col0 + warp_n*32 + n8*8 + tig*2;
            float v00 = acc[wm][n8][0], v01 = acc[wm][n8][1];
            float v10 = acc[wm][n8][2], v11 = acc[wm][n8][3];
            if (BIAS) {
                float b0 = bias[cc], b1 = bias[cc+1];
                v00 += b0; v01 += b1; v10 += b0; v11 += b1;
            }
            if (GELU) {
                v00 = 0.5f * v00 * (1.0f + erff(v00 * 0.70710678118654752f));
                v01 = 0.5f * v01 * (1.0f + erff(v01 * 0.70710678118654752f));
                v10 = 0.5f * v10 * (1.0f + erff(v10 * 0.70710678118654752f));
                v11 = 0.5f * v11 * (1.0f + erff(v11 * 0.70710678118654752f));
            }
            if (RES) {
                float2 t0 = *(const float2*)(res + (size_t)r0 * Mm + cc);
                float2 t1 = *(const float2*)(res + (size_t)r1 * Mm + cc);
                v00 += t0.x; v01 += t0.y; v10 += t1.x; v11 += t1.y;
            }
            if (OSPLIT) {
                __nv_bfloat16 h0,h1,l0,l1;
                __nv_bfloat162 p;
                split_val(v00, h0, l0); split_val(v01, h1, l1);
                p.x=h0; p.y=h1; *(__nv_bfloat162*)(Chi + (size_t)r0*Mm + cc) = p;
                p.x=l0; p.y=l1; *(__nv_bfloat162*)(Clo + (size_t)r0*Mm + cc) = p;
                split_val(v10, h0, l0); split_val(v11, h1, l1);
                p.x=h0; p.y=h1; *(__nv_bfloat162*)(Chi + (size_t)r1*Mm + cc) = p;
                p.x=l0; p.y=l1; *(__nv_bfloat162*)(Clo + (size_t)r1*Mm + cc) = p;
            } else {
                float2 o0; o0.x = v00; o0.y = v01;
                float2 o1; o1.x = v10; o1.y = v11;
                *(float2*)(C + (size_t)r0 * Mm + cc) = o0;
                *(float2*)(C + (size_t)r1 * Mm + cc) = o1;
            }
        }
    }
}

// ---------------- cross attention: block per (b,h,q-row), bf16 split out ----
__global__ void __launch_bounds__(256)
cross_attn_kernel(const float* __restrict__ q, const float* __restrict__ kv,
                  const int* __restrict__ cmask,
                  __nv_bfloat16* __restrict__ ohi, __nv_bfloat16* __restrict__ olo) {
    const int n = blockIdx.x;     // 0..4095
    const int h = blockIdx.y;     // 0..15
    const int b = blockIdx.z;     // 0..1
    const int tid = threadIdx.x;  // 256

    __shared__ float qs[64];
    __shared__ float p[Mc];
    __shared__ float red[256];

    const float* qrow = q + ((size_t)(b * TLc + n)) * 1024 + h * 64;
    if (tid < 64) qs[tid] = qrow[tid];
    __syncthreads();

    #pragma unroll
    for (int m = tid; m < Mc; m += 256) {
        float s;
        if (cmask[b * Mc + m]) {
            const float* kr = kv + ((size_t)(b * Mc + m)) * 2048 + h * 64;
            float acc = 0.f;
            #pragma unroll
            for (int d = 0; d < 64; d += 4) {
                float4 kk = *(const float4*)(kr + d);
                acc += qs[d] * kk.x + qs[d + 1] * kk.y + qs[d + 2] * kk.z + qs[d + 3] * kk.w;
            }
            s = acc * SCALEF;
        } else {
            s = NEGF;
        }
        p[m] = s;
    }
    __syncthreads();

    red[tid] = fmaxf(p[tid], p[tid + 256]);
    __syncthreads();
    for (int st = 128; st > 0; st >>= 1) {
        if (tid < st) red[tid] = fmaxf(red[tid], red[tid + st]);
        __syncthreads();
    }
    const float mx = red[0];
    __syncthreads();

    float lsum = 0.f;
    #pragma unroll
    for (int m = tid; m < Mc; m += 256) {
        float e = __expf(p[m] - mx);
        p[m] = e;
        lsum += e;
    }
    red[tid] = lsum;
    __syncthreads();
    for (int st = 128; st > 0; st >>= 1) {
        if (tid < st) red[tid] += red[tid + st];
        __syncthreads();
    }
    const float inv = 1.0f / red[0];
    __syncthreads();

    const int d = tid & 63, part = tid >> 6;
    const float* vb = kv + ((size_t)b * Mc) * 2048 + 1024 + h * 64 + d;
    float acc = 0.f;
    const int m0 = part * 128;
    #pragma unroll 8
    for (int m = m0; m < m0 + 128; m++) acc += p[m] * vb[(size_t)m * 2048];
    red[tid] = acc;
    __syncthreads();
    if (tid < 64) {
        float v = (red[tid] + red[tid + 64] + red[tid + 128] + red[tid + 192]) * inv;
        size_t off = ((size_t)(b * TLc + n)) * 1024 + h * 64 + tid;
        __nv_bfloat16 hi, lo;
        split_val(v, hi, lo);
        ohi[off] = hi;
        olo[off] = lo;
    }
}

// ---------------- temporal attention (+RoPE): block per (b,l,h), split out --
__global__ void __launch_bounds__(128)
temporal_attn_kernel(const float* __restrict__ qkv, const float* __restrict__ rope,
                     const int* __restrict__ amask,
                     __nv_bfloat16* __restrict__ othi, __nv_bfloat16* __restrict__ otlo) {
    const int l = blockIdx.x;     // 0..255
    const int h = blockIdx.y;     // 0..7
    const int b = blockIdx.z;     // 0..1
    const int tid = threadIdx.x;  // 128

    __shared__ float qs[16][64], ks[16][64], vs[16][64];
    __shared__ float ss[16][17];

    for (int idx = tid; idx < 1024; idx += 128) {
        const int t = idx >> 6, d = idx & 63;
        const size_t base = ((size_t)((b * Tc + t) * Lc + l)) * 1536 + h * 64 + d;
        qs[t][d] = qkv[base];
        ks[t][d] = qkv[base + 512];
        vs[t][d] = qkv[base + 1024];
    }
    __syncthreads();

    for (int idx = tid; idx < 256; idx += 128) {
        const int t = idx >> 4, r = idx & 15;
        const float p0 = rope[t * ROTc + r];
        const float p1 = rope[t * ROTc + r + 16];
        const float c0 = cosf(p0), s0 = sinf(p0);
        const float c1 = cosf(p1), s1 = sinf(p1);
        float a = qs[t][r], bb = qs[t][r + 16];
        qs[t][r]      = a * c0 - bb * s0;
        qs[t][r + 16] = bb * c1 + a * s1;
        a = ks[t][r]; bb = ks[t][r + 16];
        ks[t][r]      = a * c0 - bb * s0;
        ks[t][r + 16] = bb * c1 + a * s1;
    }
    __syncthreads();

    for (int idx = tid; idx < 256; idx += 128) {
        const int tq = idx >> 4, tk = idx & 15;
        float acc = 0.f;
        #pragma unroll
        for (int d = 0; d < 64; d++) acc += qs[tq][d] * ks[tk][d];
        ss[tq][tk] = amask[b * Tc + tk] ? acc * SCALEF : NEGF;
    }
    __syncthreads();

    if (tid < 16) {
        float mx = -1e30f;
        #pragma unroll
        for (int tk = 0; tk < 16; tk++) mx = fmaxf(mx, ss[tid][tk]);
        float sum = 0.f;
        #pragma unroll
        for (int tk = 0; tk < 16; tk++) { float e = __expf(ss[tid][tk] - mx); ss[tid][tk] = e; sum += e; }
        const float inv = 1.0f / sum;
        #pragma unroll
        for (int tk = 0; tk < 16; tk++) ss[tid][tk] *= inv;
    }
    __syncthreads();

    for (int idx = tid; idx < 1024; idx += 128) {
        const int tq = idx >> 6, d = idx & 63;
        float acc = 0.f;
        #pragma unroll
        for (int tk = 0; tk < 16; tk++) acc += ss[tq][tk] * vs[tk][d];
        const float qm = amask[b * Tc + tq] ? 1.0f : 0.0f;
        const float v = acc * qm;
        size_t off = ((size_t)((b * Tc + tq) * Lc + l)) * 512 + h * 64 + d;
        __nv_bfloat16 hi, lo;
        split_val(v, hi, lo);
        othi[off] = hi;
        otlo[off] = lo;
    }
}

// ---------------- launcher ----------------
extern "C" void kernel_launch(void* const* d_in, const int* in_sizes, int n_in,
                              void* d_out, int out_size) {
    const float* x        = (const float*)d_in[0];
    const float* context  = (const float*)d_in[1];
    const float* rope     = (const float*)d_in[2];
    const float* ca_ng    = (const float*)d_in[3];
    const float* ca_nb    = (const float*)d_in[4];
    const float* ca_cng   = (const float*)d_in[5];
    const float* ca_cnb   = (const float*)d_in[6];
    const float* ca_wq    = (const float*)d_in[7];
    const float* ca_wkv   = (const float*)d_in[8];
    const float* ca_wo    = (const float*)d_in[9];
    const float* ta_ng    = (const float*)d_in[10];
    const float* ta_nb    = (const float*)d_in[11];
    const float* ta_wqkv  = (const float*)d_in[12];
    const float* ta_bqkv  = (const float*)d_in[13];
    const float* ta_wo    = (const float*)d_in[14];
    const float* ff_ng    = (const float*)d_in[15];
    const float* ff_nb    = (const float*)d_in[16];
    const float* ff_w1    = (const float*)d_in[17];
    const float* ff_w2    = (const float*)d_in[18];
    const int*   cmask    = (const int*)d_in[19];
    const int*   amask    = (const int*)d_in[20];
    float* out = (float*)d_out;

    __nv_bfloat16 *xnh, *xnl, *cnh, *cnl, *och, *ocl, *hh, *hl, *wh, *wl;
    float *qb, *kvb, *qkvb, *x1, *x2;
    cudaGetSymbolAddress((void**)&xnh, g_xnh);
    cudaGetSymbolAddress((void**)&xnl, g_xnl);
    cudaGetSymbolAddress((void**)&cnh, g_cnh);
    cudaGetSymbolAddress((void**)&cnl, g_cnl);
    cudaGetSymbolAddress((void**)&och, g_och);
    cudaGetSymbolAddress((void**)&ocl, g_ocl);
    cudaGetSymbolAddress((void**)&hh,  g_hh);
    cudaGetSymbolAddress((void**)&hl,  g_hl);
    cudaGetSymbolAddress((void**)&wh,  g_wh);
    cudaGetSymbolAddress((void**)&wl,  g_wl);
    cudaGetSymbolAddress((void**)&qb,  g_q);
    cudaGetSymbolAddress((void**)&kvb, g_kv);
    cudaGetSymbolAddress((void**)&qkvb, g_qkv);
    cudaGetSymbolAddress((void**)&x1,  g_x1);
    cudaGetSymbolAddress((void**)&x2,  g_x2);

    // 0) split weights to bf16 hi/lo
    split_kernel<<<(1048576/4+255)/256, 256>>>(ca_wq,   wh+WQ_OFF,   wl+WQ_OFF,   1048576);
    split_kernel<<<(2097152/4+255)/256, 256>>>(ca_wkv,  wh+WKV_OFF,  wl+WKV_OFF,  2097152);
    split_kernel<<<(1048576/4+255)/256, 256>>>(ca_wo,   wh+WO_OFF,   wl+WO_OFF,   1048576);
    split_kernel<<<(1572864/4+255)/256, 256>>>(ta_wqkv, wh+WQKV_OFF, wl+WQKV_OFF, 1572864);
    split_kernel<<<(524288/4+255)/256, 256>>>(ta_wo,   wh+TAWO_OFF, wl+TAWO_OFF, 524288);
    split_kernel<<<(4194304/4+255)/256, 256>>>(ff_w1,   wh+FFW1_OFF, wl+FFW1_OFF, 4194304);
    split_kernel<<<(4194304/4+255)/256, 256>>>(ff_w2,   wh+FFW2_OFF, wl+FFW2_OFF, 4194304);

    // 1) xn = LN(x); cn = LN(context)
    ln_kernel<<<NR, 256>>>(x, ca_ng, ca_nb, xnh, xnl);
    ln_kernel<<<Bc * Mc, 256>>>(context, ca_cng, ca_cnb, cnh, cnl);

    // 2) q = xn @ ca_wq ; kv = cn @ ca_wkv
    bgemm_kernel<0,0,0,0><<<dim3(1024/128, NR/128), 256>>>(xnh, xnl, wh+WQ_OFF, wl+WQ_OFF,
        nullptr, nullptr, qb, nullptr, nullptr, 1024, 1024);
    bgemm_kernel<0,0,0,0><<<dim3(2048/128, 1024/128), 256>>>(cnh, cnl, wh+WKV_OFF, wl+WKV_OFF,
        nullptr, nullptr, kvb, nullptr, nullptr, 1024, 2048);

    // 3) cross attention -> och/ocl (N x 1024)
    cross_attn_kernel<<<dim3(TLc, Hc, Bc), 256>>>(qb, kvb, cmask, och, ocl);

    // 4) x1 = x + oc @ ca_wo
    bgemm_kernel<0,1,0,0><<<dim3(1024/128, NR/128), 256>>>(och, ocl, wh+WO_OFF, wl+WO_OFF,
        nullptr, x, x1, nullptr, nullptr, 1024, 1024);

    // 5) xn2 = LN(x1); qkv = xn2 @ ta_wqkv + bias
    ln_kernel<<<NR, 256>>>(x1, ta_ng, ta_nb, xnh, xnl);
    bgemm_kernel<1,0,0,0><<<dim3(1536/128, NR/128), 256>>>(xnh, xnl, wh+WQKV_OFF, wl+WQKV_OFF,
        ta_bqkv, nullptr, qkvb, nullptr, nullptr, 1024, 1536);

    // 6) temporal attention (RoPE fused) -> och/ocl reused as (N x 512)
    temporal_attn_kernel<<<dim3(Lc, HTc, Bc), 128>>>(qkvb, rope, amask, och, ocl);

    // 7) x2 = x1 + ot @ ta_wo
    bgemm_kernel<0,1,0,0><<<dim3(1024/128, NR/128), 256>>>(och, ocl, wh+TAWO_OFF, wl+TAWO_OFF,
        nullptr, x1, x2, nullptr, nullptr, 512, 1024);

    // 8) xn3 = LN(x2); h = gelu(xn3 @ ff_w1) [split out]; out = x2 + h @ ff_w2
    ln_kernel<<<NR, 256>>>(x2, ff_ng, ff_nb, xnh, xnl);
    bgemm_kernel<0,0,1,1><<<dim3(4096/128, NR/128), 256>>>(xnh, xnl, wh+FFW1_OFF, wl+FFW1_OFF,
        nullptr, nullptr, nullptr, hh, hl, 1024, 4096);
    bgemm_kernel<0,1,0,0><<<dim3(1024/128, NR/128), 256>>>(hh, hl, wh+FFW2_OFF, wl+FFW2_OFF,
        nullptr, x2, out, nullptr, nullptr, 4096, 1024);
}

// round 5
// speedup vs baseline: 2.6280x; 1.6086x over previous
#include <cuda_runtime.h>
#include <cuda_bf16.h>
#include <math.h>
#include <stdint.h>

// ---------------- problem constants ----------------
#define Bc   2
#define Tc   16
#define Lc   256
#define Mc   512
#define Dc   1024
#define Hc   16
#define DHc  64
#define HTc  8
#define ROTc 32
#define TLc  4096            // T*L
#define NR   8192            // B*T*L rows
#define SCALEF 0.125f        // 1/sqrt(64)
#define NEGF  (-1000000000.0f)

// ---------------- scratch (device globals; no allocs allowed) ----------------
__device__ __nv_bfloat16 g_xnh[(size_t)NR * Dc];
__device__ __nv_bfloat16 g_xnl[(size_t)NR * Dc];
__device__ __nv_bfloat16 g_cnh[(size_t)1024 * Dc];
__device__ __nv_bfloat16 g_cnl[(size_t)1024 * Dc];
__device__ __nv_bfloat16 g_och[(size_t)NR * Dc];   // cross out (Nx1024), reused temporal (Nx512)
__device__ __nv_bfloat16 g_ocl[(size_t)NR * Dc];
__device__ __nv_bfloat16 g_hh [(size_t)NR * 4096];
__device__ __nv_bfloat16 g_hl [(size_t)NR * 4096];
// bf16 split weights (concatenated)
#define WQ_OFF    0
#define WKV_OFF   1048576
#define WO_OFF    3145728
#define WQKV_OFF  4194304
#define TAWO_OFF  5767168
#define FFW1_OFF  6291456
#define FFW2_OFF  10485760
#define WTOTAL    14680064
__device__ __nv_bfloat16 g_wh[WTOTAL];
__device__ __nv_bfloat16 g_wl[WTOTAL];
// fp32 buffers
__device__ float g_q  [(size_t)NR * Dc];
__device__ float g_kv [(size_t)1024 * 2048];
__device__ float g_qkv[(size_t)NR * 1536];
__device__ float g_x1 [(size_t)NR * Dc];
__device__ float g_x2 [(size_t)NR * Dc];

// ---------------- helpers ----------------
__device__ __forceinline__ void split_val(float v, __nv_bfloat16& hi, __nv_bfloat16& lo) {
    hi = __float2bfloat16_rn(v);
    lo = __float2bfloat16_rn(v - __bfloat162float(hi));
}

__device__ __forceinline__ void ldsm_x4(uint32_t* r, uint32_t addr) {
    asm volatile("ldmatrix.sync.aligned.m8n8.x4.shared.b16 {%0,%1,%2,%3}, [%4];"
        : "=r"(r[0]), "=r"(r[1]), "=r"(r[2]), "=r"(r[3]) : "r"(addr));
}
__device__ __forceinline__ void ldsm_x4_t(uint32_t* r, uint32_t addr) {
    asm volatile("ldmatrix.sync.aligned.m8n8.x4.trans.shared.b16 {%0,%1,%2,%3}, [%4];"
        : "=r"(r[0]), "=r"(r[1]), "=r"(r[2]), "=r"(r[3]) : "r"(addr));
}
__device__ __forceinline__ void mma_bf16(float* c, const uint32_t* a, uint32_t b0, uint32_t b1) {
    asm volatile("mma.sync.aligned.m16n8k16.row.col.f32.bf16.bf16.f32 "
        "{%0,%1,%2,%3},{%4,%5,%6,%7},{%8,%9},{%0,%1,%2,%3};"
        : "+f"(c[0]), "+f"(c[1]), "+f"(c[2]), "+f"(c[3])
        : "r"(a[0]), "r"(a[1]), "r"(a[2]), "r"(a[3]), "r"(b0), "r"(b1));
}

// ---------------- weight split kernel ----------------
__global__ void split_kernel(const float* __restrict__ w, __nv_bfloat16* __restrict__ hi,
                             __nv_bfloat16* __restrict__ lo, int n) {
    int i = (blockIdx.x * blockDim.x + threadIdx.x) * 4;
    if (i >= n) return;
    float4 v = *(const float4*)(w + i);
    __nv_bfloat16 h0, h1, h2, h3, l0, l1, l2, l3;
    split_val(v.x, h0, l0); split_val(v.y, h1, l1);
    split_val(v.z, h2, l2); split_val(v.w, h3, l3);
    __nv_bfloat162 a, b;
    a.x = h0; a.y = h1; b.x = h2; b.y = h3;
    *(__nv_bfloat162*)(hi + i) = a; *(__nv_bfloat162*)(hi + i + 2) = b;
    a.x = l0; a.y = l1; b.x = l2; b.y = l3;
    *(__nv_bfloat162*)(lo + i) = a; *(__nv_bfloat162*)(lo + i + 2) = b;
}

// ---------------- LayerNorm: one block per row, D=1024, bf16 split out ------
__global__ void ln_kernel(const float* __restrict__ x, const float* __restrict__ g,
                          const float* __restrict__ b,
                          __nv_bfloat16* __restrict__ yh, __nv_bfloat16* __restrict__ yl) {
    const int row = blockIdx.x;
    const int tid = threadIdx.x;                 // 256 threads
    const float4* xr = (const float4*)(x + (size_t)row * Dc);
    float4 v = xr[tid];
    float s  = v.x + v.y + v.z + v.w;
    float ss = v.x*v.x + v.y*v.y + v.z*v.z + v.w*v.w;

    __shared__ float rs[8], rss[8];
    for (int o = 16; o > 0; o >>= 1) {
        s  += __shfl_down_sync(0xffffffff, s,  o);
        ss += __shfl_down_sync(0xffffffff, ss, o);
    }
    const int wid = tid >> 5, lane = tid & 31;
    if (lane == 0) { rs[wid] = s; rss[wid] = ss; }
    __syncthreads();
    if (tid == 0) {
        float ts = 0.f, tss = 0.f;
        #pragma unroll
        for (int i = 0; i < 8; i++) { ts += rs[i]; tss += rss[i]; }
        rs[0] = ts; rss[0] = tss;
    }
    __syncthreads();
    const float mean = rs[0] * (1.0f / Dc);
    const float var  = rss[0] * (1.0f / Dc) - mean * mean;
    const float inv  = rsqrtf(var + 1e-5f);

    float4 gg = ((const float4*)g)[tid];
    float4 bb = ((const float4*)b)[tid];
    float o0 = (v.x - mean) * inv * gg.x + bb.x;
    float o1 = (v.y - mean) * inv * gg.y + bb.y;
    float o2 = (v.z - mean) * inv * gg.z + bb.z;
    float o3 = (v.w - mean) * inv * gg.w + bb.w;
    __nv_bfloat16 h0,h1,h2,h3,l0,l1,l2,l3;
    split_val(o0,h0,l0); split_val(o1,h1,l1); split_val(o2,h2,l2); split_val(o3,h3,l3);
    size_t off = (size_t)row * Dc + tid * 4;
    __nv_bfloat162 p;
    p.x=h0; p.y=h1; *(__nv_bfloat162*)(yh+off)   = p;
    p.x=h2; p.y=h3; *(__nv_bfloat162*)(yh+off+2) = p;
    p.x=l0; p.y=l1; *(__nv_bfloat162*)(yl+off)   = p;
    p.x=l2; p.y=l3; *(__nv_bfloat162*)(yl+off+2) = p;
}

// ---------------- split-bf16 tensor-core GEMM -------------------------------
#define ASTR 48
#define BSTR 272
#define ASZ  (128*ASTR)
#define BSZ  (16*BSTR)
#define SMEM_A_TOT (2*2*ASZ)
#define SMEM_B_TOT (2*2*BSZ)

template<int BIAS, int RES, int GELU, int OSPLIT>
__global__ void __launch_bounds__(256, 1)
bgemm_kernel(const __nv_bfloat16* __restrict__ Ahi, const __nv_bfloat16* __restrict__ Alo,
             const __nv_bfloat16* __restrict__ Bhi, const __nv_bfloat16* __restrict__ Blo,
             const float* __restrict__ bias, const float* __restrict__ res,
             float* __restrict__ C, __nv_bfloat16* __restrict__ Chi, __nv_bfloat16* __restrict__ Clo,
             int K, int Mm) {
    __shared__ __align__(16) unsigned char smem[SMEM_A_TOT + SMEM_B_TOT];

    const int tid  = threadIdx.x;
    const int lane = tid & 31, wid = tid >> 5;
    const int warp_m = wid & 1, warp_n = wid >> 1;   // 2 x 4
    const int row0 = blockIdx.y * 128, col0 = blockIdx.x * 128;

    const int a_m = tid >> 1, a_k = (tid & 1) * 8;
    const int b_k = tid >> 4, b_n = (tid & 15) * 8;
    const __nv_bfloat16* pAh = Ahi + (size_t)(row0 + a_m) * K + a_k;
    const __nv_bfloat16* pAl = Alo + (size_t)(row0 + a_m) * K + a_k;
    const __nv_bfloat16* pBh = Bhi + (size_t)b_k * Mm + col0 + b_n;
    const __nv_bfloat16* pBl = Blo + (size_t)b_k * Mm + col0 + b_n;
    const int sa = a_m * ASTR + a_k * 2;
    const int sb = b_k * BSTR + b_n * 2;

    uint4 rah = *(const uint4*)pAh;
    uint4 ral = *(const uint4*)pAl;
    uint4 rbh = *(const uint4*)pBh;
    uint4 rbl = *(const uint4*)pBl;
    *(uint4*)(smem + 0*ASZ + sa) = rah;
    *(uint4*)(smem + 1*ASZ + sa) = ral;
    *(uint4*)(smem + SMEM_A_TOT + 0*BSZ + sb) = rbh;
    *(uint4*)(smem + SMEM_A_TOT + 1*BSZ + sb) = rbl;
    __syncthreads();

    float acc[4][4][4];
    #pragma unroll
    for (int i = 0; i < 4; i++)
        #pragma unroll
        for (int j = 0; j < 4; j++)
            #pragma unroll
            for (int k = 0; k < 4; k++) acc[i][j][k] = 0.f;

    const uint32_t sbase = (uint32_t)__cvta_generic_to_shared(smem);
    const uint32_t aAddr = sbase + (uint32_t)((warp_m*64 + (lane & 15)) * ASTR + (lane >> 4) * 16);
    const uint32_t bAddr = sbase + SMEM_A_TOT
                         + (uint32_t)((lane & 15) * BSTR + (warp_n*32 + (lane >> 4)*8) * 2);

    const int nsteps = K >> 4;
    for (int s = 0; s < nsteps; s++) {
        const int buf = s & 1;
        const bool more = (s + 1) < nsteps;
        if (more) {
            rah = *(const uint4*)(pAh + (size_t)(s+1) * 16);
            ral = *(const uint4*)(pAl + (size_t)(s+1) * 16);
            rbh = *(const uint4*)(pBh + (size_t)(s+1) * 16 * Mm);
            rbl = *(const uint4*)(pBl + (size_t)(s+1) * 16 * Mm);
        }

        uint32_t ah[4][4], al[4][4], bh[2][4], bl[2][4];
        const uint32_t aoffH = (uint32_t)((buf*2 + 0) * ASZ);
        const uint32_t aoffL = (uint32_t)((buf*2 + 1) * ASZ);
        const uint32_t boffH = (uint32_t)((buf*2 + 0) * BSZ);
        const uint32_t boffL = (uint32_t)((buf*2 + 1) * BSZ);
        #pragma unroll
        for (int wm = 0; wm < 4; wm++) {
            ldsm_x4(ah[wm], aAddr + aoffH + wm * 16 * ASTR);
            ldsm_x4(al[wm], aAddr + aoffL + wm * 16 * ASTR);
        }
        #pragma unroll
        for (int bn = 0; bn < 2; bn++) {
            ldsm_x4_t(bh[bn], bAddr + boffH + bn * 32);
            ldsm_x4_t(bl[bn], bAddr + boffL + bn * 32);
        }

        #pragma unroll
        for (int wm = 0; wm < 4; wm++) {
            #pragma unroll
            for (int bn = 0; bn < 2; bn++) {
                #pragma unroll
                for (int half = 0; half < 2; half++) {
                    float* c = acc[wm][bn*2 + half];
                    const uint32_t h0 = bh[bn][half*2], h1 = bh[bn][half*2+1];
                    const uint32_t l0 = bl[bn][half*2], l1 = bl[bn][half*2+1];
                    mma_bf16(c, ah[wm], h0, h1);
                    mma_bf16(c, ah[wm], l0, l1);
                    mma_bf16(c, al[wm], h0, h1);
                }
            }
        }

        if (more) {
            const int nb = buf ^ 1;
            *(uint4*)(smem + (nb*2 + 0)*ASZ + sa) = rah;
            *(uint4*)(smem + (nb*2 + 1)*ASZ + sa) = ral;
            *(uint4*)(smem + SMEM_A_TOT + (nb*2 + 0)*BSZ + sb) = rbh;
            *(uint4*)(smem + SMEM_A_TOT + (nb*2 + 1)*BSZ + sb) = rbl;
            __syncthreads();
        }
    }

    const int gID = lane >> 2, tig = lane & 3;
    #pragma unroll
    for (int wm = 0; wm < 4; wm++) {
        const int r0 = row0 + warp_m*64 + wm*16 + gID;
        const int r1 = r0 + 8;
        #pragma unroll
        for (int n8 = 0; n8 < 4; n8++) {
            const int cc = col0 + warp_n*32 + n8*8 + tig*2;
            float v00 = acc[wm][n8][0], v01 = acc[wm][n8][1];
            float v10 = acc[wm][n8][2], v11 = acc[wm][n8][3];
            if (BIAS) {
                float b0 = bias[cc], b1 = bias[cc+1];
                v00 += b0; v01 += b1; v10 += b0; v11 += b1;
            }
            if (GELU) {
                v00 = 0.5f * v00 * (1.0f + erff(v00 * 0.70710678118654752f));
                v01 = 0.5f * v01 * (1.0f + erff(v01 * 0.70710678118654752f));
                v10 = 0.5f * v10 * (1.0f + erff(v10 * 0.70710678118654752f));
                v11 = 0.5f * v11 * (1.0f + erff(v11 * 0.70710678118654752f));
            }
            if (RES) {
                float2 t0 = *(const float2*)(res + (size_t)r0 * Mm + cc);
                float2 t1 = *(const float2*)(res + (size_t)r1 * Mm + cc);
                v00 += t0.x; v01 += t0.y; v10 += t1.x; v11 += t1.y;
            }
            if (OSPLIT) {
                __nv_bfloat16 h0,h1,l0,l1;
                __nv_bfloat162 p;
                split_val(v00, h0, l0); split_val(v01, h1, l1);
                p.x=h0; p.y=h1; *(__nv_bfloat162*)(Chi + (size_t)r0*Mm + cc) = p;
                p.x=l0; p.y=l1; *(__nv_bfloat162*)(Clo + (size_t)r0*Mm + cc) = p;
                split_val(v10, h0, l0); split_val(v11, h1, l1);
                p.x=h0; p.y=h1; *(__nv_bfloat162*)(Chi + (size_t)r1*Mm + cc) = p;
                p.x=l0; p.y=l1; *(__nv_bfloat162*)(Clo + (size_t)r1*Mm + cc) = p;
            } else {
                float2 o0; o0.x = v00; o0.y = v01;
                float2 o1; o1.x = v10; o1.y = v11;
                *(float2*)(C + (size_t)r0 * Mm + cc) = o0;
                *(float2*)(C + (size_t)r1 * Mm + cc) = o1;
            }
        }
    }
}

// ---------------- cross attention v2: flash-style, block per (b,h,64-query tile) ----
// Grid (64, 16, 2), 256 threads. K/V streamed in 32-key chunks via smem.
// Thread (qi = tid>>2, dg = tid&3) owns O[16] dims [dg*16, dg*16+16) of query qi.
__global__ void __launch_bounds__(256)
cross_attn_kernel(const float* __restrict__ q, const float* __restrict__ kv,
                  const int* __restrict__ cmask,
                  __nv_bfloat16* __restrict__ ohi, __nv_bfloat16* __restrict__ olo) {
    const int n0 = blockIdx.x * 64;
    const int h = blockIdx.y;
    const int b = blockIdx.z;
    const int tid = threadIdx.x;

    __shared__ float Qs[64][68];
    __shared__ float Ks[32][68];
    __shared__ float Vs[32][68];
    __shared__ float Ss[64][33];

    // load Q tile (64 x 64)
    {
        const float* qbase = q + ((size_t)(b * TLc + n0)) * 1024 + h * 64;
        #pragma unroll
        for (int i = tid; i < 1024; i += 256) {
            const int r = i >> 4, c4 = (i & 15) << 2;
            *(float4*)&Qs[r][c4] = *(const float4*)(qbase + (size_t)r * 1024 + c4);
        }
    }

    const int qi = tid >> 2, dg = tid & 3;
    const int ty = tid >> 4, tx = tid & 15;       // score-tile mapping
    float O[16];
    #pragma unroll
    for (int i = 0; i < 16; i++) O[i] = 0.f;
    float mval = -1e30f, lval = 0.f;

    for (int m0 = 0; m0 < Mc; m0 += 32) {
        __syncthreads();   // prior chunk fully consumed
        // load K,V chunk (32 x 64 each)
        const float* kbase = kv + ((size_t)(b * Mc + m0)) * 2048 + h * 64;
        #pragma unroll
        for (int i = tid; i < 512; i += 256) {
            const int r = i >> 4, c4 = (i & 15) << 2;
            *(float4*)&Ks[r][c4] = *(const float4*)(kbase + (size_t)r * 2048 + c4);
            *(float4*)&Vs[r][c4] = *(const float4*)(kbase + (size_t)r * 2048 + 1024 + c4);
        }
        __syncthreads();

        // scores: 64x32 tile; thread (ty,tx) -> rows ty*4+i, cols tx*2+j
        float acc[4][2] = {};
        #pragma unroll
        for (int d4 = 0; d4 < 64; d4 += 4) {
            float4 b0 = *(const float4*)&Ks[tx*2+0][d4];
            float4 b1 = *(const float4*)&Ks[tx*2+1][d4];
            #pragma unroll
            for (int i = 0; i < 4; i++) {
                float4 a = *(const float4*)&Qs[ty*4+i][d4];
                acc[i][0] += a.x*b0.x + a.y*b0.y + a.z*b0.z + a.w*b0.w;
                acc[i][1] += a.x*b1.x + a.y*b1.y + a.z*b1.z + a.w*b1.w;
            }
        }
        const int msk0 = cmask[b * Mc + m0 + tx*2];
        const int msk1 = cmask[b * Mc + m0 + tx*2 + 1];
        #pragma unroll
        for (int i = 0; i < 4; i++) {
            Ss[ty*4+i][tx*2+0] = msk0 ? acc[i][0] * SCALEF : NEGF;
            Ss[ty*4+i][tx*2+1] = msk1 ? acc[i][1] * SCALEF : NEGF;
        }
        __syncthreads();

        // online softmax update for row qi (4 threads/row, 8 cols each)
        float cmax = -1e30f;
        #pragma unroll
        for (int k = 0; k < 8; k++) cmax = fmaxf(cmax, Ss[qi][dg*8+k]);
        cmax = fmaxf(cmax, __shfl_xor_sync(0xffffffff, cmax, 1));
        cmax = fmaxf(cmax, __shfl_xor_sync(0xffffffff, cmax, 2));
        const float nm = fmaxf(mval, cmax);
        const float alpha = __expf(mval - nm);
        float psum = 0.f;
        #pragma unroll
        for (int k = 0; k < 8; k++) {
            float e = __expf(Ss[qi][dg*8+k] - nm);
            Ss[qi][dg*8+k] = e;
            psum += e;
        }
        psum += __shfl_xor_sync(0xffffffff, psum, 1);
        psum += __shfl_xor_sync(0xffffffff, psum, 2);
        lval = lval * alpha + psum;
        mval = nm;
        #pragma unroll
        for (int i = 0; i < 16; i++) O[i] *= alpha;
        __syncwarp();      // e-values of this row visible within the 4-lane group's warp

        // PV accumulate
        #pragma unroll
        for (int k = 0; k < 32; k++) {
            const float e = Ss[qi][k];
            float4 v0 = *(const float4*)&Vs[k][dg*16+0];
            float4 v1 = *(const float4*)&Vs[k][dg*16+4];
            float4 v2 = *(const float4*)&Vs[k][dg*16+8];
            float4 v3 = *(const float4*)&Vs[k][dg*16+12];
            O[0]  += e*v0.x; O[1]  += e*v0.y; O[2]  += e*v0.z; O[3]  += e*v0.w;
            O[4]  += e*v1.x; O[5]  += e*v1.y; O[6]  += e*v1.z; O[7]  += e*v1.w;
            O[8]  += e*v2.x; O[9]  += e*v2.y; O[10] += e*v2.z; O[11] += e*v2.w;
            O[12] += e*v3.x; O[13] += e*v3.y; O[14] += e*v3.z; O[15] += e*v3.w;
        }
    }

    const float inv = 1.0f / lval;
    const size_t off = ((size_t)(b * TLc + n0 + qi)) * 1024 + h * 64 + dg * 16;
    #pragma unroll
    for (int i = 0; i < 16; i += 2) {
        float v0 = O[i] * inv, v1 = O[i+1] * inv;
        __nv_bfloat16 h0, l0, h1, l1;
        split_val(v0, h0, l0); split_val(v1, h1, l1);
        __nv_bfloat162 ph, pl;
        ph.x = h0; ph.y = h1;
        pl.x = l0; pl.y = l1;
        *(__nv_bfloat162*)(ohi + off + i) = ph;
        *(__nv_bfloat162*)(olo + off + i) = pl;
    }
}

// ---------------- temporal attention (+RoPE): block per (b,l,h), split out --
__global__ void __launch_bounds__(128)
temporal_attn_kernel(const float* __restrict__ qkv, const float* __restrict__ rope,
                     const int* __restrict__ amask,
                     __nv_bfloat16* __restrict__ othi, __nv_bfloat16* __restrict__ otlo) {
    const int l = blockIdx.x;
    const int h = blockIdx.y;
    const int b = blockIdx.z;
    const int tid = threadIdx.x;  // 128

    __shared__ float qs[16][64], ks[16][64], vs[16][64];
    __shared__ float ss[16][17];

    for (int idx = tid; idx < 1024; idx += 128) {
        const int t = idx >> 6, d = idx & 63;
        const size_t base = ((size_t)((b * Tc + t) * Lc + l)) * 1536 + h * 64 + d;
        qs[t][d] = qkv[base];
        ks[t][d] = qkv[base + 512];
        vs[t][d] = qkv[base + 1024];
    }
    __syncthreads();

    for (int idx = tid; idx < 256; idx += 128) {
        const int t = idx >> 4, r = idx & 15;
        const float p0 = rope[t * ROTc + r];
        const float p1 = rope[t * ROTc + r + 16];
        const float c0 = cosf(p0), s0 = sinf(p0);
        const float c1 = cosf(p1), s1 = sinf(p1);
        float a = qs[t][r], bb = qs[t][r + 16];
        qs[t][r]      = a * c0 - bb * s0;
        qs[t][r + 16] = bb * c1 + a * s1;
        a = ks[t][r]; bb = ks[t][r + 16];
        ks[t][r]      = a * c0 - bb * s0;
        ks[t][r + 16] = bb * c1 + a * s1;
    }
    __syncthreads();

    for (int idx = tid; idx < 256; idx += 128) {
        const int tq = idx >> 4, tk = idx & 15;
        float acc = 0.f;
        #pragma unroll
        for (int d = 0; d < 64; d++) acc += qs[tq][d] * ks[tk][d];
        ss[tq][tk] = amask[b * Tc + tk] ? acc * SCALEF : NEGF;
    }
    __syncthreads();

    if (tid < 16) {
        float mx = -1e30f;
        #pragma unroll
        for (int tk = 0; tk < 16; tk++) mx = fmaxf(mx, ss[tid][tk]);
        float sum = 0.f;
        #pragma unroll
        for (int tk = 0; tk < 16; tk++) { float e = __expf(ss[tid][tk] - mx); ss[tid][tk] = e; sum += e; }
        const float inv = 1.0f / sum;
        #pragma unroll
        for (int tk = 0; tk < 16; tk++) ss[tid][tk] *= inv;
    }
    __syncthreads();

    for (int idx = tid; idx < 1024; idx += 128) {
        const int tq = idx >> 6, d = idx & 63;
        float acc = 0.f;
        #pragma unroll
        for (int tk = 0; tk < 16; tk++) acc += ss[tq][tk] * vs[tk][d];
        const float qm = amask[b * Tc + tq] ? 1.0f : 0.0f;
        const float v = acc * qm;
        size_t off = ((size_t)((b * Tc + tq) * Lc + l)) * 512 + h * 64 + d;
        __nv_bfloat16 hi, lo;
        split_val(v, hi, lo);
        othi[off] = hi;
        otlo[off] = lo;
    }
}

// ---------------- launcher ----------------
extern "C" void kernel_launch(void* const* d_in, const int* in_sizes, int n_in,
                              void* d_out, int out_size) {
    const float* x        = (const float*)d_in[0];
    const float* context  = (const float*)d_in[1];
    const float* rope     = (const float*)d_in[2];
    const float* ca_ng    = (const float*)d_in[3];
    const float* ca_nb    = (const float*)d_in[4];
    const float* ca_cng   = (const float*)d_in[5];
    const float* ca_cnb   = (const float*)d_in[6];
    const float* ca_wq    = (const float*)d_in[7];
    const float* ca_wkv   = (const float*)d_in[8];
    const float* ca_wo    = (const float*)d_in[9];
    const float* ta_ng    = (const float*)d_in[10];
    const float* ta_nb    = (const float*)d_in[11];
    const float* ta_wqkv  = (const float*)d_in[12];
    const float* ta_bqkv  = (const float*)d_in[13];
    const float* ta_wo    = (const float*)d_in[14];
    const float* ff_ng    = (const float*)d_in[15];
    const float* ff_nb    = (const float*)d_in[16];
    const float* ff_w1    = (const float*)d_in[17];
    const float* ff_w2    = (const float*)d_in[18];
    const int*   cmask    = (const int*)d_in[19];
    const int*   amask    = (const int*)d_in[20];
    float* out = (float*)d_out;

    __nv_bfloat16 *xnh, *xnl, *cnh, *cnl, *och, *ocl, *hh, *hl, *wh, *wl;
    float *qb, *kvb, *qkvb, *x1, *x2;
    cudaGetSymbolAddress((void**)&xnh, g_xnh);
    cudaGetSymbolAddress((void**)&xnl, g_xnl);
    cudaGetSymbolAddress((void**)&cnh, g_cnh);
    cudaGetSymbolAddress((void**)&cnl, g_cnl);
    cudaGetSymbolAddress((void**)&och, g_och);
    cudaGetSymbolAddress((void**)&ocl, g_ocl);
    cudaGetSymbolAddress((void**)&hh,  g_hh);
    cudaGetSymbolAddress((void**)&hl,  g_hl);
    cudaGetSymbolAddress((void**)&wh,  g_wh);
    cudaGetSymbolAddress((void**)&wl,  g_wl);
    cudaGetSymbolAddress((void**)&qb,  g_q);
    cudaGetSymbolAddress((void**)&kvb, g_kv);
    cudaGetSymbolAddress((void**)&qkvb, g_qkv);
    cudaGetSymbolAddress((void**)&x1,  g_x1);
    cudaGetSymbolAddress((void**)&x2,  g_x2);

    // 0) split weights to bf16 hi/lo
    split_kernel<<<(1048576/4+255)/256, 256>>>(ca_wq,   wh+WQ_OFF,   wl+WQ_OFF,   1048576);
    split_kernel<<<(2097152/4+255)/256, 256>>>(ca_wkv,  wh+WKV_OFF,  wl+WKV_OFF,  2097152);
    split_kernel<<<(1048576/4+255)/256, 256>>>(ca_wo,   wh+WO_OFF,   wl+WO_OFF,   1048576);
    split_kernel<<<(1572864/4+255)/256, 256>>>(ta_wqkv, wh+WQKV_OFF, wl+WQKV_OFF, 1572864);
    split_kernel<<<(524288/4+255)/256, 256>>>(ta_wo,   wh+TAWO_OFF, wl+TAWO_OFF, 524288);
    split_kernel<<<(4194304/4+255)/256, 256>>>(ff_w1,   wh+FFW1_OFF, wl+FFW1_OFF, 4194304);
    split_kernel<<<(4194304/4+255)/256, 256>>>(ff_w2,   wh+FFW2_OFF, wl+FFW2_OFF, 4194304);

    // 1) xn = LN(x); cn = LN(context)
    ln_kernel<<<NR, 256>>>(x, ca_ng, ca_nb, xnh, xnl);
    ln_kernel<<<Bc * Mc, 256>>>(context, ca_cng, ca_cnb, cnh, cnl);

    // 2) q = xn @ ca_wq ; kv = cn @ ca_wkv
    bgemm_kernel<0,0,0,0><<<dim3(1024/128, NR/128), 256>>>(xnh, xnl, wh+WQ_OFF, wl+WQ_OFF,
        nullptr, nullptr, qb, nullptr, nullptr, 1024, 1024);
    bgemm_kernel<0,0,0,0><<<dim3(2048/128, 1024/128), 256>>>(cnh, cnl, wh+WKV_OFF, wl+WKV_OFF,
        nullptr, nullptr, kvb, nullptr, nullptr, 1024, 2048);

    // 3) cross attention (flash-style) -> och/ocl (N x 1024)
    cross_attn_kernel<<<dim3(TLc/64, Hc, Bc), 256>>>(qb, kvb, cmask, och, ocl);

    // 4) x1 = x + oc @ ca_wo
    bgemm_kernel<0,1,0,0><<<dim3(1024/128, NR/128), 256>>>(och, ocl, wh+WO_OFF, wl+WO_OFF,
        nullptr, x, x1, nullptr, nullptr, 1024, 1024);

    // 5) xn2 = LN(x1); qkv = xn2 @ ta_wqkv + bias
    ln_kernel<<<NR, 256>>>(x1, ta_ng, ta_nb, xnh, xnl);
    bgemm_kernel<1,0,0,0><<<dim3(1536/128, NR/128), 256>>>(xnh, xnl, wh+WQKV_OFF, wl+WQKV_OFF,
        ta_bqkv, nullptr, qkvb, nullptr, nullptr, 1024, 1536);

    // 6) temporal attention (RoPE fused) -> och/ocl reused as (N x 512)
    temporal_attn_kernel<<<dim3(Lc, HTc, Bc), 128>>>(qkvb, rope, amask, och, ocl);

    // 7) x2 = x1 + ot @ ta_wo
    bgemm_kernel<0,1,0,0><<<dim3(1024/128, NR/128), 256>>>(och, ocl, wh+TAWO_OFF, wl+TAWO_OFF,
        nullptr, x1, x2, nullptr, nullptr, 512, 1024);

    // 8) xn3 = LN(x2); h = gelu(xn3 @ ff_w1) [split out]; out = x2 + h @ ff_w2
    ln_kernel<<<NR, 256>>>(x2, ff_ng, ff_nb, xnh, xnl);
    bgemm_kernel<0,0,1,1><<<dim3(4096/128, NR/128), 256>>>(xnh, xnl, wh+FFW1_OFF, wl+FFW1_OFF,
        nullptr, nullptr, nullptr, hh, hl, 1024, 4096);
    bgemm_kernel<0,1,0,0><<<dim3(1024/128, NR/128), 256>>>(hh, hl, wh+FFW2_OFF, wl+FFW2_OFF,
        nullptr, x2, out, nullptr, nullptr, 4096, 1024);
}

// round 7
// speedup vs baseline: 2.6628x; 1.0132x over previous
#include <cuda_runtime.h>
#include <cuda_bf16.h>
#include <math.h>
#include <stdint.h>

// ---------------- problem constants ----------------
#define Bc   2
#define Tc   16
#define Lc   256
#define Mc   512
#define Dc   1024
#define Hc   16
#define HTc  8
#define ROTc 32
#define TLc  4096
#define NR   8192
#define SCALEF 0.125f
#define NEGF  (-1000000000.0f)

// ---------------- scratch ----------------
__device__ __nv_bfloat16 g_xnh[(size_t)NR * Dc];
__device__ __nv_bfloat16 g_xnl[(size_t)NR * Dc];
__device__ __nv_bfloat16 g_cnh[(size_t)1024 * Dc];
__device__ __nv_bfloat16 g_cnl[(size_t)1024 * Dc];
__device__ __nv_bfloat16 g_och[(size_t)NR * Dc];
__device__ __nv_bfloat16 g_ocl[(size_t)NR * Dc];
__device__ __nv_bfloat16 g_hh [(size_t)NR * 4096];
__device__ __nv_bfloat16 g_hl [(size_t)NR * 4096];
// split weights [K][N] (no transpose; ldmatrix.trans handles it)
#define WQ_OFF    0
#define WKV_OFF   1048576
#define WO_OFF    3145728
#define WQKV_OFF  4194304
#define TAWO_OFF  5767168
#define FFW1_OFF  6291456
#define FFW2_OFF  10485760
#define WTOTAL    14680064
__device__ __nv_bfloat16 g_wh[WTOTAL];
__device__ __nv_bfloat16 g_wl[WTOTAL];
// fp32 buffers
__device__ float g_q  [(size_t)NR * Dc];
__device__ float g_kv [(size_t)1024 * 2048];
__device__ float g_qkv[(size_t)NR * 1536];
__device__ float g_x1 [(size_t)NR * Dc];
__device__ float g_x2 [(size_t)NR * Dc];

// ---------------- helpers ----------------
__device__ __forceinline__ void split_val(float v, __nv_bfloat16& hi, __nv_bfloat16& lo) {
    hi = __float2bfloat16_rn(v);
    lo = __float2bfloat16_rn(v - __bfloat162float(hi));
}
__device__ __forceinline__ void ldsm_x4(uint32_t* r, uint32_t addr) {
    asm volatile("ldmatrix.sync.aligned.m8n8.x4.shared.b16 {%0,%1,%2,%3}, [%4];"
        : "=r"(r[0]), "=r"(r[1]), "=r"(r[2]), "=r"(r[3]) : "r"(addr));
}
__device__ __forceinline__ void ldsm_x4_t(uint32_t* r, uint32_t addr) {
    asm volatile("ldmatrix.sync.aligned.m8n8.x4.trans.shared.b16 {%0,%1,%2,%3}, [%4];"
        : "=r"(r[0]), "=r"(r[1]), "=r"(r[2]), "=r"(r[3]) : "r"(addr));
}
__device__ __forceinline__ void mma_bf16(float* c, const uint32_t* a, uint32_t b0, uint32_t b1) {
    asm volatile("mma.sync.aligned.m16n8k16.row.col.f32.bf16.bf16.f32 "
        "{%0,%1,%2,%3},{%4,%5,%6,%7},{%8,%9},{%0,%1,%2,%3};"
        : "+f"(c[0]), "+f"(c[1]), "+f"(c[2]), "+f"(c[3])
        : "r"(a[0]), "r"(a[1]), "r"(a[2]), "r"(a[3]), "r"(b0), "r"(b1));
}
__device__ __forceinline__ void cpa16(uint32_t dst, const void* src) {
    asm volatile("cp.async.cg.shared.global [%0], [%1], 16;" :: "r"(dst), "l"(src));
}

// ---------------- weight split kernel (plain, [K][N] layout kept) -----------
__global__ void split_kernel(const float* __restrict__ w, __nv_bfloat16* __restrict__ hi,
                             __nv_bfloat16* __restrict__ lo, int n) {
    int i = (blockIdx.x * blockDim.x + threadIdx.x) * 4;
    if (i >= n) return;
    float4 v = *(const float4*)(w + i);
    __nv_bfloat16 h0, h1, h2, h3, l0, l1, l2, l3;
    split_val(v.x, h0, l0); split_val(v.y, h1, l1);
    split_val(v.z, h2, l2); split_val(v.w, h3, l3);
    __nv_bfloat162 a, b;
    a.x = h0; a.y = h1; b.x = h2; b.y = h3;
    *(__nv_bfloat162*)(hi + i) = a; *(__nv_bfloat162*)(hi + i + 2) = b;
    a.x = l0; a.y = l1; b.x = l2; b.y = l3;
    *(__nv_bfloat162*)(lo + i) = a; *(__nv_bfloat162*)(lo + i + 2) = b;
}

// ---------------- LayerNorm ----------------
__global__ void ln_kernel(const float* __restrict__ x, const float* __restrict__ g,
                          const float* __restrict__ b,
                          __nv_bfloat16* __restrict__ yh, __nv_bfloat16* __restrict__ yl) {
    const int row = blockIdx.x;
    const int tid = threadIdx.x;
    const float4* xr = (const float4*)(x + (size_t)row * Dc);
    float4 v = xr[tid];
    float s  = v.x + v.y + v.z + v.w;
    float ss = v.x*v.x + v.y*v.y + v.z*v.z + v.w*v.w;

    __shared__ float rs[8], rss[8];
    for (int o = 16; o > 0; o >>= 1) {
        s  += __shfl_down_sync(0xffffffff, s,  o);
        ss += __shfl_down_sync(0xffffffff, ss, o);
    }
    const int wid = tid >> 5, lane = tid & 31;
    if (lane == 0) { rs[wid] = s; rss[wid] = ss; }
    __syncthreads();
    if (tid == 0) {
        float ts = 0.f, tss = 0.f;
        #pragma unroll
        for (int i = 0; i < 8; i++) { ts += rs[i]; tss += rss[i]; }
        rs[0] = ts; rss[0] = tss;
    }
    __syncthreads();
    const float mean = rs[0] * (1.0f / Dc);
    const float var  = rss[0] * (1.0f / Dc) - mean * mean;
    const float inv  = rsqrtf(var + 1e-5f);

    float4 gg = ((const float4*)g)[tid];
    float4 bb = ((const float4*)b)[tid];
    float o0 = (v.x - mean) * inv * gg.x + bb.x;
    float o1 = (v.y - mean) * inv * gg.y + bb.y;
    float o2 = (v.z - mean) * inv * gg.z + bb.z;
    float o3 = (v.w - mean) * inv * gg.w + bb.w;
    __nv_bfloat16 h0,h1,h2,h3,l0,l1,l2,l3;
    split_val(o0,h0,l0); split_val(o1,h1,l1); split_val(o2,h2,l2); split_val(o3,h3,l3);
    size_t off = (size_t)row * Dc + tid * 4;
    __nv_bfloat162 p;
    p.x=h0; p.y=h1; *(__nv_bfloat162*)(yh+off)   = p;
    p.x=h2; p.y=h3; *(__nv_bfloat162*)(yh+off+2) = p;
    p.x=l0; p.y=l1; *(__nv_bfloat162*)(yl+off)   = p;
    p.x=l2; p.y=l3; *(__nv_bfloat162*)(yl+off+2) = p;
}

// ---------------- split-bf16 mma.sync GEMM, cp.async 3-stage, BK=32 ---------
// C[N,Mm] = (Ahi+Alo)[N,K] @ (Bhi+Blo)[K,Mm]  (+bias) (gelu) (+res)
#define BKc   32
#define ASTR  80              // 32 bf16 (64B) + 16B pad
#define BSTR  272             // 128 bf16 (256B) + 16B pad
#define A_SZ  (128*ASTR)      // 10240
#define B_SZ  (32*BSTR)       // 8704
#define ST_A  (2*A_SZ)        // 20480
#define ST_B  (2*B_SZ)        // 17408
#define STAGE (ST_A+ST_B)     // 37888
#define NSTG  3
#define GEMM_SMEM (NSTG*STAGE)  // 113664

template<int BIAS, int RES, int GELU, int OSPLIT>
__global__ void __launch_bounds__(256, 1)
bgemm_kernel(const __nv_bfloat16* __restrict__ Ahi, const __nv_bfloat16* __restrict__ Alo,
             const __nv_bfloat16* __restrict__ Bhi, const __nv_bfloat16* __restrict__ Blo,
             const float* __restrict__ bias, const float* __restrict__ res,
             float* __restrict__ C, __nv_bfloat16* __restrict__ Chi, __nv_bfloat16* __restrict__ Clo,
             int K, int Mm) {
    extern __shared__ __align__(16) unsigned char sm[];
    const uint32_t sb = (uint32_t)__cvta_generic_to_shared(sm);

    const int tid  = threadIdx.x;
    const int lane = tid & 31, wid = tid >> 5;
    const int warp_m = wid & 1, warp_n = wid >> 1;   // 2 x 4
    const int row0 = blockIdx.y * 128, col0 = blockIdx.x * 128;

    const __nv_bfloat16* pA[2] = {Ahi, Alo};
    const __nv_bfloat16* pB[2] = {Bhi, Blo};
    const int nsteps = K / BKc;

    // per-thread load mapping
    const int a_row = tid >> 1;                 // pairs: c = tid + 256*i -> row=c>>2? use explicit below
    (void)a_row;

    auto load_stage = [&](int s) {
        const uint32_t base = sb + (uint32_t)((s % NSTG) * STAGE);
        const int k0 = s * BKc;
        #pragma unroll
        for (int arr = 0; arr < 2; arr++) {
            // A: 128 rows x 32 k, 4 x 16B chunks per row, 512 chunks, 2/thread
            #pragma unroll
            for (int i = 0; i < 2; i++) {
                const int c = tid + 256 * i;
                const int r = c >> 2, kc = c & 3;
                cpa16(base + (uint32_t)(arr * A_SZ + r * ASTR + kc * 16),
                      pA[arr] + (size_t)(row0 + r) * K + k0 + kc * 8);
            }
            // B: 32 k-rows x 128 n, 16 x 16B chunks per row, 512 chunks, 2/thread
            #pragma unroll
            for (int i = 0; i < 2; i++) {
                const int c = tid + 256 * i;
                const int r = c >> 4, nc = c & 15;
                cpa16(base + (uint32_t)(ST_A + arr * B_SZ + r * BSTR + nc * 16),
                      pB[arr] + (size_t)(k0 + r) * Mm + col0 + nc * 8);
            }
        }
    };

    float acc[4][4][4];
    #pragma unroll
    for (int i = 0; i < 4; i++)
        #pragma unroll
        for (int j = 0; j < 4; j++)
            #pragma unroll
            for (int k = 0; k < 4; k++) acc[i][j][k] = 0.f;

    // prologue: stages 0,1 in flight
    load_stage(0);
    asm volatile("cp.async.commit_group;" ::: "memory");
    load_stage(1);
    asm volatile("cp.async.commit_group;" ::: "memory");

    const uint32_t aLane = (uint32_t)((warp_m * 64 + (lane & 15)) * ASTR + (lane >> 4) * 16);
    const uint32_t bLane = (uint32_t)(ST_A + (lane & 15) * BSTR + (warp_n * 32 + (lane >> 4) * 8) * 2);

    for (int s = 0; s < nsteps; s++) {
        if (s + 2 < nsteps) load_stage(s + 2);
        asm volatile("cp.async.commit_group;" ::: "memory");
        asm volatile("cp.async.wait_group 2;" ::: "memory");
        __syncthreads();

        const uint32_t base = sb + (uint32_t)((s % NSTG) * STAGE);
        #pragma unroll
        for (int c = 0; c < 2; c++) {          // two k16 chunks in BK=32
            uint32_t ah[4][4], al[4][4], bh[2][4], bl[2][4];
            const uint32_t aA = base + aLane + (uint32_t)(c * 32);
            const uint32_t bA = base + bLane + (uint32_t)(c * 16 * BSTR);
            #pragma unroll
            for (int wm = 0; wm < 4; wm++) {
                ldsm_x4(ah[wm], aA + (uint32_t)(wm * 16 * ASTR));
                ldsm_x4(al[wm], aA + (uint32_t)(A_SZ + wm * 16 * ASTR));
            }
            #pragma unroll
            for (int bn = 0; bn < 2; bn++) {
                ldsm_x4_t(bh[bn], bA + (uint32_t)(bn * 32));
                ldsm_x4_t(bl[bn], bA + (uint32_t)(B_SZ + bn * 32));
            }
            #pragma unroll
            for (int wm = 0; wm < 4; wm++) {
                #pragma unroll
                for (int bn = 0; bn < 2; bn++) {
                    #pragma unroll
                    for (int half = 0; half < 2; half++) {
                        float* cc = acc[wm][bn*2 + half];
                        const uint32_t h0 = bh[bn][half*2], h1 = bh[bn][half*2+1];
                        const uint32_t l0 = bl[bn][half*2], l1 = bl[bn][half*2+1];
                        mma_bf16(cc, ah[wm], h0, h1);
                        mma_bf16(cc, ah[wm], l0, l1);
                        mma_bf16(cc, al[wm], h0, h1);
                    }
                }
            }
        }
        __syncthreads();   // protect slot reuse by the next load_stage
    }

    // epilogue
    const int gID = lane >> 2, tig = lane & 3;
    #pragma unroll
    for (int wm = 0; wm < 4; wm++) {
        const int r0 = row0 + warp_m*64 + wm*16 + gID;
        const int r1 = r0 + 8;
        #pragma unroll
        for (int n8 = 0; n8 < 4; n8++) {
            const int cc = col0 + warp_n*32 + n8*8 + tig*2;
            float v00 = acc[wm][n8][0], v01 = acc[wm][n8][1];
            float v10 = acc[wm][n8][2], v11 = acc[wm][n8][3];
            if (BIAS) {
                float b0 = bias[cc], b1 = bias[cc+1];
                v00 += b0; v01 += b1; v10 += b0; v11 += b1;
            }
            if (GELU) {
                v00 = 0.5f * v00 * (1.0f + erff(v00 * 0.70710678118654752f));
                v01 = 0.5f * v01 * (1.0f + erff(v01 * 0.70710678118654752f));
                v10 = 0.5f * v10 * (1.0f + erff(v10 * 0.70710678118654752f));
                v11 = 0.5f * v11 * (1.0f + erff(v11 * 0.70710678118654752f));
            }
            if (RES) {
                float2 t0 = *(const float2*)(res + (size_t)r0 * Mm + cc);
                float2 t1 = *(const float2*)(res + (size_t)r1 * Mm + cc);
                v00 += t0.x; v01 += t0.y; v10 += t1.x; v11 += t1.y;
            }
            if (OSPLIT) {
                __nv_bfloat16 h0,h1,l0,l1;
                __nv_bfloat162 p;
                split_val(v00, h0, l0); split_val(v01, h1, l1);
                p.x=h0; p.y=h1; *(__nv_bfloat162*)(Chi + (size_t)r0*Mm + cc) = p;
                p.x=l0; p.y=l1; *(__nv_bfloat162*)(Clo + (size_t)r0*Mm + cc) = p;
                split_val(v10, h0, l0); split_val(v11, h1, l1);
                p.x=h0; p.y=h1; *(__nv_bfloat162*)(Chi + (size_t)r1*Mm + cc) = p;
                p.x=l0; p.y=l1; *(__nv_bfloat162*)(Clo + (size_t)r1*Mm + cc) = p;
            } else {
                float2 o0; o0.x = v00; o0.y = v01;
                float2 o1; o1.x = v10; o1.y = v11;
                *(float2*)(C + (size_t)r0 * Mm + cc) = o0;
                *(float2*)(C + (size_t)r1 * Mm + cc) = o1;
            }
        }
    }
}

// ---------------- cross attention (flash-style) -----------------------------
__global__ void __launch_bounds__(256)
cross_attn_kernel(const float* __restrict__ q, const float* __restrict__ kv,
                  const int* __restrict__ cmask,
                  __nv_bfloat16* __restrict__ ohi, __nv_bfloat16* __restrict__ olo) {
    const int n0 = blockIdx.x * 64;
    const int h = blockIdx.y;
    const int b = blockIdx.z;
    const int tid = threadIdx.x;

    __shared__ float Qs[64][68];
    __shared__ float Ks[32][68];
    __shared__ float Vs[32][68];
    __shared__ float Ss[64][33];

    {
        const float* qbase = q + ((size_t)(b * TLc + n0)) * 1024 + h * 64;
        #pragma unroll
        for (int i = tid; i < 1024; i += 256) {
            const int r = i >> 4, c4 = (i & 15) << 2;
            *(float4*)&Qs[r][c4] = *(const float4*)(qbase + (size_t)r * 1024 + c4);
        }
    }

    const int qi = tid >> 2, dg = tid & 3;
    const int ty = tid >> 4, tx = tid & 15;
    float O[16];
    #pragma unroll
    for (int i = 0; i < 16; i++) O[i] = 0.f;
    float mval = -1e30f, lval = 0.f;

    for (int m0 = 0; m0 < Mc; m0 += 32) {
        __syncthreads();
        const float* kbase = kv + ((size_t)(b * Mc + m0)) * 2048 + h * 64;
        #pragma unroll
        for (int i = tid; i < 512; i += 256) {
            const int r = i >> 4, c4 = (i & 15) << 2;
            *(float4*)&Ks[r][c4] = *(const float4*)(kbase + (size_t)r * 2048 + c4);
            *(float4*)&Vs[r][c4] = *(const float4*)(kbase + (size_t)r * 2048 + 1024 + c4);
        }
        __syncthreads();

        float acc[4][2] = {};
        #pragma unroll
        for (int d4 = 0; d4 < 64; d4 += 4) {
            float4 b0 = *(const float4*)&Ks[tx*2+0][d4];
            float4 b1 = *(const float4*)&Ks[tx*2+1][d4];
            #pragma unroll
            for (int i = 0; i < 4; i++) {
                float4 a = *(const float4*)&Qs[ty*4+i][d4];
                acc[i][0] += a.x*b0.x + a.y*b0.y + a.z*b0.z + a.w*b0.w;
                acc[i][1] += a.x*b1.x + a.y*b1.y + a.z*b1.z + a.w*b1.w;
            }
        }
        const int msk0 = cmask[b * Mc + m0 + tx*2];
        const int msk1 = cmask[b * Mc + m0 + tx*2 + 1];
        #pragma unroll
        for (int i = 0; i < 4; i++) {
            Ss[ty*4+i][tx*2+0] = msk0 ? acc[i][0] * SCALEF : NEGF;
            Ss[ty*4+i][tx*2+1] = msk1 ? acc[i][1] * SCALEF : NEGF;
        }
        __syncthreads();

        float cmax = -1e30f;
        #pragma unroll
        for (int k = 0; k < 8; k++) cmax = fmaxf(cmax, Ss[qi][dg*8+k]);
        cmax = fmaxf(cmax, __shfl_xor_sync(0xffffffff, cmax, 1));
        cmax = fmaxf(cmax, __shfl_xor_sync(0xffffffff, cmax, 2));
        const float nm = fmaxf(mval, cmax);
        const float alpha = __expf(mval - nm);
        float psum = 0.f;
        #pragma unroll
        for (int k = 0; k < 8; k++) {
            float e = __expf(Ss[qi][dg*8+k] - nm);
            Ss[qi][dg*8+k] = e;
            psum += e;
        }
        psum += __shfl_xor_sync(0xffffffff, psum, 1);
        psum += __shfl_xor_sync(0xffffffff, psum, 2);
        lval = lval * alpha + psum;
        mval = nm;
        #pragma unroll
        for (int i = 0; i < 16; i++) O[i] *= alpha;
        __syncwarp();

        #pragma unroll
        for (int k = 0; k < 32; k++) {
            const float e = Ss[qi][k];
            float4 v0 = *(const float4*)&Vs[k][dg*16+0];
            float4 v1 = *(const float4*)&Vs[k][dg*16+4];
            float4 v2 = *(const float4*)&Vs[k][dg*16+8];
            float4 v3 = *(const float4*)&Vs[k][dg*16+12];
            O[0]  += e*v0.x; O[1]  += e*v0.y; O[2]  += e*v0.z; O[3]  += e*v0.w;
            O[4]  += e*v1.x; O[5]  += e*v1.y; O[6]  += e*v1.z; O[7]  += e*v1.w;
            O[8]  += e*v2.x; O[9]  += e*v2.y; O[10] += e*v2.z; O[11] += e*v2.w;
            O[12] += e*v3.x; O[13] += e*v3.y; O[14] += e*v3.z; O[15] += e*v3.w;
        }
    }

    const float inv = 1.0f / lval;
    const size_t off = ((size_t)(b * TLc + n0 + qi)) * 1024 + h * 64 + dg * 16;
    #pragma unroll
    for (int i = 0; i < 16; i += 2) {
        float v0 = O[i] * inv, v1 = O[i+1] * inv;
        __nv_bfloat16 h0, l0, h1, l1;
        split_val(v0, h0, l0); split_val(v1, h1, l1);
        __nv_bfloat162 ph, pl;
        ph.x = h0; ph.y = h1;
        pl.x = l0; pl.y = l1;
        *(__nv_bfloat162*)(ohi + off + i) = ph;
        *(__nv_bfloat162*)(olo + off + i) = pl;
    }
}

// ---------------- temporal attention (+RoPE) --------------------------------
__global__ void __launch_bounds__(128)
temporal_attn_kernel(const float* __restrict__ qkv, const float* __restrict__ rope,
                     const int* __restrict__ amask,
                     __nv_bfloat16* __restrict__ othi, __nv_bfloat16* __restrict__ otlo) {
    const int l = blockIdx.x;
    const int h = blockIdx.y;
    const int b = blockIdx.z;
    const int tid = threadIdx.x;

    __shared__ float qs[16][64], ks[16][64], vs[16][64];
    __shared__ float ss[16][17];

    for (int idx = tid; idx < 1024; idx += 128) {
        const int t = idx >> 6, d = idx & 63;
        const size_t base = ((size_t)((b * Tc + t) * Lc + l)) * 1536 + h * 64 + d;
        qs[t][d] = qkv[base];
        ks[t][d] = qkv[base + 512];
        vs[t][d] = qkv[base + 1024];
    }
    __syncthreads();

    for (int idx = tid; idx < 256; idx += 128) {
        const int t = idx >> 4, r = idx & 15;
        const float p0 = rope[t * ROTc + r];
        const float p1 = rope[t * ROTc + r + 16];
        const float c0 = cosf(p0), s0 = sinf(p0);
        const float c1 = cosf(p1), s1 = sinf(p1);
        float a = qs[t][r], bb = qs[t][r + 16];
        qs[t][r]      = a * c0 - bb * s0;
        qs[t][r + 16] = bb * c1 + a * s1;
        a = ks[t][r]; bb = ks[t][r + 16];
        ks[t][r]      = a * c0 - bb * s0;
        ks[t][r + 16] = bb * c1 + a * s1;
    }
    __syncthreads();

    for (int idx = tid; idx < 256; idx += 128) {
        const int tq = idx >> 4, tk = idx & 15;
        float acc = 0.f;
        #pragma unroll
        for (int d = 0; d < 64; d++) acc += qs[tq][d] * ks[tk][d];
        ss[tq][tk] = amask[b * Tc + tk] ? acc * SCALEF : NEGF;
    }
    __syncthreads();

    if (tid < 16) {
        float mx = -1e30f;
        #pragma unroll
        for (int tk = 0; tk < 16; tk++) mx = fmaxf(mx, ss[tid][tk]);
        float sum = 0.f;
        #pragma unroll
        for (int tk = 0; tk < 16; tk++) { float e = __expf(ss[tid][tk] - mx); ss[tid][tk] = e; sum += e; }
        const float inv = 1.0f / sum;
        #pragma unroll
        for (int tk = 0; tk < 16; tk++) ss[tid][tk] *= inv;
    }
    __syncthreads();

    for (int idx = tid; idx < 1024; idx += 128) {
        const int tq = idx >> 6, d = idx & 63;
        float acc = 0.f;
        #pragma unroll
        for (int tk = 0; tk < 16; tk++) acc += ss[tq][tk] * vs[tk][d];
        const float qm = amask[b * Tc + tq] ? 1.0f : 0.0f;
        const float v = acc * qm;
        size_t off = ((size_t)((b * Tc + tq) * Lc + l)) * 512 + h * 64 + d;
        __nv_bfloat16 hi, lo;
        split_val(v, hi, lo);
        othi[off] = hi;
        otlo[off] = lo;
    }
}

// ---------------- launcher ----------------
extern "C" void kernel_launch(void* const* d_in, const int* in_sizes, int n_in,
                              void* d_out, int out_size) {
    const float* x        = (const float*)d_in[0];
    const float* context  = (const float*)d_in[1];
    const float* rope     = (const float*)d_in[2];
    const float* ca_ng    = (const float*)d_in[3];
    const float* ca_nb    = (const float*)d_in[4];
    const float* ca_cng   = (const float*)d_in[5];
    const float* ca_cnb   = (const float*)d_in[6];
    const float* ca_wq    = (const float*)d_in[7];
    const float* ca_wkv   = (const float*)d_in[8];
    const float* ca_wo    = (const float*)d_in[9];
    const float* ta_ng    = (const float*)d_in[10];
    const float* ta_nb    = (const float*)d_in[11];
    const float* ta_wqkv  = (const float*)d_in[12];
    const float* ta_bqkv  = (const float*)d_in[13];
    const float* ta_wo    = (const float*)d_in[14];
    const float* ff_ng    = (const float*)d_in[15];
    const float* ff_nb    = (const float*)d_in[16];
    const float* ff_w1    = (const float*)d_in[17];
    const float* ff_w2    = (const float*)d_in[18];
    const int*   cmask    = (const int*)d_in[19];
    const int*   amask    = (const int*)d_in[20];
    float* out = (float*)d_out;

    __nv_bfloat16 *xnh, *xnl, *cnh, *cnl, *och, *ocl, *hh, *hl, *wh, *wl;
    float *qb, *kvb, *qkvb, *x1, *x2;
    cudaGetSymbolAddress((void**)&xnh, g_xnh);
    cudaGetSymbolAddress((void**)&xnl, g_xnl);
    cudaGetSymbolAddress((void**)&cnh, g_cnh);
    cudaGetSymbolAddress((void**)&cnl, g_cnl);
    cudaGetSymbolAddress((void**)&och, g_och);
    cudaGetSymbolAddress((void**)&ocl, g_ocl);
    cudaGetSymbolAddress((void**)&hh,  g_hh);
    cudaGetSymbolAddress((void**)&hl,  g_hl);
    cudaGetSymbolAddress((void**)&wh,  g_wh);
    cudaGetSymbolAddress((void**)&wl,  g_wl);
    cudaGetSymbolAddress((void**)&qb,  g_q);
    cudaGetSymbolAddress((void**)&kvb, g_kv);
    cudaGetSymbolAddress((void**)&qkvb, g_qkv);
    cudaGetSymbolAddress((void**)&x1,  g_x1);
    cudaGetSymbolAddress((void**)&x2,  g_x2);

    // opt-in dynamic smem (host-side, idempotent)
    cudaFuncSetAttribute(bgemm_kernel<0,0,0,0>, cudaFuncAttributeMaxDynamicSharedMemorySize, GEMM_SMEM);
    cudaFuncSetAttribute(bgemm_kernel<0,1,0,0>, cudaFuncAttributeMaxDynamicSharedMemorySize, GEMM_SMEM);
    cudaFuncSetAttribute(bgemm_kernel<1,0,0,0>, cudaFuncAttributeMaxDynamicSharedMemorySize, GEMM_SMEM);
    cudaFuncSetAttribute(bgemm_kernel<0,0,1,1>, cudaFuncAttributeMaxDynamicSharedMemorySize, GEMM_SMEM);

    // 0) split weights to bf16 hi/lo ([K][N] kept)
    split_kernel<<<(1048576/4+255)/256, 256>>>(ca_wq,   wh+WQ_OFF,   wl+WQ_OFF,   1048576);
    split_kernel<<<(2097152/4+255)/256, 256>>>(ca_wkv,  wh+WKV_OFF,  wl+WKV_OFF,  2097152);
    split_kernel<<<(1048576/4+255)/256, 256>>>(ca_wo,   wh+WO_OFF,   wl+WO_OFF,   1048576);
    split_kernel<<<(1572864/4+255)/256, 256>>>(ta_wqkv, wh+WQKV_OFF, wl+WQKV_OFF, 1572864);
    split_kernel<<<(524288/4+255)/256, 256>>>(ta_wo,   wh+TAWO_OFF, wl+TAWO_OFF, 524288);
    split_kernel<<<(4194304/4+255)/256, 256>>>(ff_w1,   wh+FFW1_OFF, wl+FFW1_OFF, 4194304);
    split_kernel<<<(4194304/4+255)/256, 256>>>(ff_w2,   wh+FFW2_OFF, wl+FFW2_OFF, 4194304);

    // 1) xn = LN(x); cn = LN(context)
    ln_kernel<<<NR, 256>>>(x, ca_ng, ca_nb, xnh, xnl);
    ln_kernel<<<Bc * Mc, 256>>>(context, ca_cng, ca_cnb, cnh, cnl);

    // 2) q = xn @ ca_wq ; kv = cn @ ca_wkv
    bgemm_kernel<0,0,0,0><<<dim3(1024/128, NR/128), 256, GEMM_SMEM>>>(
        xnh, xnl, wh+WQ_OFF, wl+WQ_OFF, nullptr, nullptr, qb, nullptr, nullptr, 1024, 1024);
    bgemm_kernel<0,0,0,0><<<dim3(2048/128, 1024/128), 256, GEMM_SMEM>>>(
        cnh, cnl, wh+WKV_OFF, wl+WKV_OFF, nullptr, nullptr, kvb, nullptr, nullptr, 1024, 2048);

    // 3) cross attention -> och/ocl (N x 1024)
    cross_attn_kernel<<<dim3(TLc/64, Hc, Bc), 256>>>(qb, kvb, cmask, och, ocl);

    // 4) x1 = x + oc @ ca_wo
    bgemm_kernel<0,1,0,0><<<dim3(1024/128, NR/128), 256, GEMM_SMEM>>>(
        och, ocl, wh+WO_OFF, wl+WO_OFF, nullptr, x, x1, nullptr, nullptr, 1024, 1024);

    // 5) xn2 = LN(x1); qkv = xn2 @ ta_wqkv + bias
    ln_kernel<<<NR, 256>>>(x1, ta_ng, ta_nb, xnh, xnl);
    bgemm_kernel<1,0,0,0><<<dim3(1536/128, NR/128), 256, GEMM_SMEM>>>(
        xnh, xnl, wh+WQKV_OFF, wl+WQKV_OFF, ta_bqkv, nullptr, qkvb, nullptr, nullptr, 1024, 1536);

    // 6) temporal attention -> och/ocl reused as (N x 512)
    temporal_attn_kernel<<<dim3(Lc, HTc, Bc), 128>>>(qkvb, rope, amask, och, ocl);

    // 7) x2 = x1 + ot @ ta_wo
    bgemm_kernel<0,1,0,0><<<dim3(1024/128, NR/128), 256, GEMM_SMEM>>>(
        och, ocl, wh+TAWO_OFF, wl+TAWO_OFF, nullptr, x1, x2, nullptr, nullptr, 512, 1024);

    // 8) xn3 = LN(x2); h = gelu(xn3 @ ff_w1) [split]; out = x2 + h @ ff_w2
    ln_kernel<<<NR, 256>>>(x2, ff_ng, ff_nb, xnh, xnl);
    bgemm_kernel<0,0,1,1><<<dim3(4096/128, NR/128), 256, GEMM_SMEM>>>(
        xnh, xnl, wh+FFW1_OFF, wl+FFW1_OFF, nullptr, nullptr, nullptr, hh, hl, 1024, 4096);
    bgemm_kernel<0,1,0,0><<<dim3(1024/128, NR/128), 256, GEMM_SMEM>>>(
        hh, hl, wh+FFW2_OFF, wl+FFW2_OFF, nullptr, x2, out, nullptr, nullptr, 4096, 1024);
}

// round 8
// speedup vs baseline: 4.0898x; 1.5359x over previous
#include <cuda_runtime.h>
#include <cuda_fp16.h>
#include <math.h>
#include <stdint.h>

// ---------------- problem constants ----------------
#define Bc   2
#define Tc   16
#define Lc   256
#define Mc   512
#define Dc   1024
#define Hc   16
#define HTc  8
#define ROTc 32
#define TLc  4096
#define NR   8192
#define SCALEF 0.125f
#define NEGF  (-1000000000.0f)

// ---------------- scratch ----------------
__device__ __half g_xn[(size_t)NR * Dc];
__device__ __half g_cn[(size_t)1024 * Dc];
__device__ __half g_oc[(size_t)NR * Dc];     // cross out (Nx1024), temporal out (Nx512)
__device__ __half g_h [(size_t)NR * 4096];
// fp16 weights [K][N]
#define WQ_OFF    0
#define WKV_OFF   1048576
#define WO_OFF    3145728
#define WQKV_OFF  4194304
#define TAWO_OFF  5767168
#define FFW1_OFF  6291456
#define FFW2_OFF  10485760
#define WTOTAL    14680064
__device__ __half g_w[WTOTAL];
// fp32 buffers
__device__ float g_q  [(size_t)NR * Dc];
__device__ float g_kv [(size_t)1024 * 2048];
__device__ float g_qkv[(size_t)NR * 1536];
__device__ float g_x1 [(size_t)NR * Dc];
__device__ float g_x2 [(size_t)NR * Dc];

// ---------------- helpers ----------------
__device__ __forceinline__ void ldsm_x4(uint32_t* r, uint32_t addr) {
    asm volatile("ldmatrix.sync.aligned.m8n8.x4.shared.b16 {%0,%1,%2,%3}, [%4];"
        : "=r"(r[0]), "=r"(r[1]), "=r"(r[2]), "=r"(r[3]) : "r"(addr));
}
__device__ __forceinline__ void ldsm_x4_t(uint32_t* r, uint32_t addr) {
    asm volatile("ldmatrix.sync.aligned.m8n8.x4.trans.shared.b16 {%0,%1,%2,%3}, [%4];"
        : "=r"(r[0]), "=r"(r[1]), "=r"(r[2]), "=r"(r[3]) : "r"(addr));
}
__device__ __forceinline__ void mma_f16(float* c, const uint32_t* a, uint32_t b0, uint32_t b1) {
    asm volatile("mma.sync.aligned.m16n8k16.row.col.f32.f16.f16.f32 "
        "{%0,%1,%2,%3},{%4,%5,%6,%7},{%8,%9},{%0,%1,%2,%3};"
        : "+f"(c[0]), "+f"(c[1]), "+f"(c[2]), "+f"(c[3])
        : "r"(a[0]), "r"(a[1]), "r"(a[2]), "r"(a[3]), "r"(b0), "r"(b1));
}
__device__ __forceinline__ void cpa16(uint32_t dst, const void* src) {
    asm volatile("cp.async.cg.shared.global [%0], [%1], 16;" :: "r"(dst), "l"(src));
}

// ---------------- fp32 -> fp16 convert kernel ----------------
__global__ void tohalf_kernel(const float* __restrict__ w, __half* __restrict__ o, int n) {
    int i = (blockIdx.x * blockDim.x + threadIdx.x) * 4;
    if (i >= n) return;
    float4 v = *(const float4*)(w + i);
    __half2 a, b;
    a.x = __float2half_rn(v.x); a.y = __float2half_rn(v.y);
    b.x = __float2half_rn(v.z); b.y = __float2half_rn(v.w);
    *(__half2*)(o + i) = a; *(__half2*)(o + i + 2) = b;
}

// ---------------- LayerNorm -> fp16 out ----------------
__global__ void ln_kernel(const float* __restrict__ x, const float* __restrict__ g,
                          const float* __restrict__ b, __half* __restrict__ y) {
    const int row = blockIdx.x;
    const int tid = threadIdx.x;
    const float4* xr = (const float4*)(x + (size_t)row * Dc);
    float4 v = xr[tid];
    float s  = v.x + v.y + v.z + v.w;
    float ss = v.x*v.x + v.y*v.y + v.z*v.z + v.w*v.w;

    __shared__ float rs[8], rss[8];
    for (int o = 16; o > 0; o >>= 1) {
        s  += __shfl_down_sync(0xffffffff, s,  o);
        ss += __shfl_down_sync(0xffffffff, ss, o);
    }
    const int wid = tid >> 5, lane = tid & 31;
    if (lane == 0) { rs[wid] = s; rss[wid] = ss; }
    __syncthreads();
    if (tid == 0) {
        float ts = 0.f, tss = 0.f;
        #pragma unroll
        for (int i = 0; i < 8; i++) { ts += rs[i]; tss += rss[i]; }
        rs[0] = ts; rss[0] = tss;
    }
    __syncthreads();
    const float mean = rs[0] * (1.0f / Dc);
    const float var  = rss[0] * (1.0f / Dc) - mean * mean;
    const float inv  = rsqrtf(var + 1e-5f);

    float4 gg = ((const float4*)g)[tid];
    float4 bb = ((const float4*)b)[tid];
    __half2 p0, p1;
    p0.x = __float2half_rn((v.x - mean) * inv * gg.x + bb.x);
    p0.y = __float2half_rn((v.y - mean) * inv * gg.y + bb.y);
    p1.x = __float2half_rn((v.z - mean) * inv * gg.z + bb.z);
    p1.y = __float2half_rn((v.w - mean) * inv * gg.w + bb.w);
    size_t off = (size_t)row * Dc + tid * 4;
    *(__half2*)(y + off)     = p0;
    *(__half2*)(y + off + 2) = p1;
}

// ---------------- fp16 mma.sync GEMM, cp.async 3-stage, BK=64 ---------------
// C[N,Mm] = A[N,K] @ B[K,Mm]  (+bias) (gelu) (+res); optional fp16 out
#define BKc   64
#define ASTR  144             // 64 f16 (128B) + 16B pad
#define BSTR  272             // 128 f16 (256B) + 16B pad
#define A_SZ  (128*ASTR)      // 18432
#define B_SZ  (64*BSTR)       // 17408
#define STAGE (A_SZ+B_SZ)     // 35840
#define NSTG  3
#define GEMM_SMEM (NSTG*STAGE)  // 107520

template<int BIAS, int RES, int GELU, int OHALF>
__global__ void __launch_bounds__(256, 1)
bgemm_kernel(const __half* __restrict__ A, const __half* __restrict__ B,
             const float* __restrict__ bias, const float* __restrict__ res,
             float* __restrict__ C, __half* __restrict__ Ch,
             int K, int Mm) {
    extern __shared__ __align__(16) unsigned char sm[];
    const uint32_t sb = (uint32_t)__cvta_generic_to_shared(sm);

    const int tid  = threadIdx.x;
    const int lane = tid & 31, wid = tid >> 5;
    const int warp_m = wid & 1, warp_n = wid >> 1;   // 2 x 4
    const int row0 = blockIdx.y * 128, col0 = blockIdx.x * 128;
    const int nsteps = K / BKc;

    auto load_stage = [&](int s) {
        const uint32_t base = sb + (uint32_t)((s % NSTG) * STAGE);
        const int k0 = s * BKc;
        // A: 128 rows x 8 16B-chunks = 1024, 4/thread
        #pragma unroll
        for (int i = 0; i < 4; i++) {
            const int c = tid + 256 * i;
            const int r = c >> 3, kc = c & 7;
            cpa16(base + (uint32_t)(r * ASTR + kc * 16),
                  A + (size_t)(row0 + r) * K + k0 + kc * 8);
        }
        // B: 64 k-rows x 16 16B-chunks = 1024, 4/thread
        #pragma unroll
        for (int i = 0; i < 4; i++) {
            const int c = tid + 256 * i;
            const int r = c >> 4, nc = c & 15;
            cpa16(base + (uint32_t)(A_SZ + r * BSTR + nc * 16),
                  B + (size_t)(k0 + r) * Mm + col0 + nc * 8);
        }
    };

    float acc[4][4][4];
    #pragma unroll
    for (int i = 0; i < 4; i++)
        #pragma unroll
        for (int j = 0; j < 4; j++)
            #pragma unroll
            for (int k = 0; k < 4; k++) acc[i][j][k] = 0.f;

    load_stage(0);
    asm volatile("cp.async.commit_group;" ::: "memory");
    load_stage(1);
    asm volatile("cp.async.commit_group;" ::: "memory");

    const uint32_t aLane = (uint32_t)((warp_m * 64 + (lane & 15)) * ASTR + (lane >> 4) * 16);
    const uint32_t bLane = (uint32_t)(A_SZ + (lane & 15) * BSTR + (warp_n * 32 + (lane >> 4) * 8) * 2);

    for (int s = 0; s < nsteps; s++) {
        if (s + 2 < nsteps) load_stage(s + 2);
        asm volatile("cp.async.commit_group;" ::: "memory");
        asm volatile("cp.async.wait_group 2;" ::: "memory");
        __syncthreads();

        const uint32_t base = sb + (uint32_t)((s % NSTG) * STAGE);
        #pragma unroll
        for (int c = 0; c < 4; c++) {          // four k16 chunks in BK=64
            uint32_t ah[4][4], bh[2][4];
            const uint32_t aA = base + aLane + (uint32_t)(c * 32);
            const uint32_t bA = base + bLane + (uint32_t)(c * 16 * BSTR);
            #pragma unroll
            for (int wm = 0; wm < 4; wm++)
                ldsm_x4(ah[wm], aA + (uint32_t)(wm * 16 * ASTR));
            #pragma unroll
            for (int bn = 0; bn < 2; bn++)
                ldsm_x4_t(bh[bn], bA + (uint32_t)(bn * 32));
            #pragma unroll
            for (int wm = 0; wm < 4; wm++) {
                #pragma unroll
                for (int bn = 0; bn < 2; bn++) {
                    #pragma unroll
                    for (int half = 0; half < 2; half++) {
                        mma_f16(acc[wm][bn*2 + half], ah[wm],
                                bh[bn][half*2], bh[bn][half*2+1]);
                    }
                }
            }
        }
        __syncthreads();
    }

    // epilogue
    const int gID = lane >> 2, tig = lane & 3;
    #pragma unroll
    for (int wm = 0; wm < 4; wm++) {
        const int r0 = row0 + warp_m*64 + wm*16 + gID;
        const int r1 = r0 + 8;
        #pragma unroll
        for (int n8 = 0; n8 < 4; n8++) {
            const int cc = col0 + warp_n*32 + n8*8 + tig*2;
            float v00 = acc[wm][n8][0], v01 = acc[wm][n8][1];
            float v10 = acc[wm][n8][2], v11 = acc[wm][n8][3];
            if (BIAS) {
                float b0 = bias[cc], b1 = bias[cc+1];
                v00 += b0; v01 += b1; v10 += b0; v11 += b1;
            }
            if (GELU) {
                v00 = 0.5f * v00 * (1.0f + erff(v00 * 0.70710678118654752f));
                v01 = 0.5f * v01 * (1.0f + erff(v01 * 0.70710678118654752f));
                v10 = 0.5f * v10 * (1.0f + erff(v10 * 0.70710678118654752f));
                v11 = 0.5f * v11 * (1.0f + erff(v11 * 0.70710678118654752f));
            }
            if (RES) {
                float2 t0 = *(const float2*)(res + (size_t)r0 * Mm + cc);
                float2 t1 = *(const float2*)(res + (size_t)r1 * Mm + cc);
                v00 += t0.x; v01 += t0.y; v10 += t1.x; v11 += t1.y;
            }
            if (OHALF) {
                __half2 p0, p1;
                p0.x = __float2half_rn(v00); p0.y = __float2half_rn(v01);
                p1.x = __float2half_rn(v10); p1.y = __float2half_rn(v11);
                *(__half2*)(Ch + (size_t)r0 * Mm + cc) = p0;
                *(__half2*)(Ch + (size_t)r1 * Mm + cc) = p1;
            } else {
                float2 o0; o0.x = v00; o0.y = v01;
                float2 o1; o1.x = v10; o1.y = v11;
                *(float2*)(C + (size_t)r0 * Mm + cc) = o0;
                *(float2*)(C + (size_t)r1 * Mm + cc) = o1;
            }
        }
    }
}

// ---------------- cross attention (flash-style), fp16 out ------------------
__global__ void __launch_bounds__(256)
cross_attn_kernel(const float* __restrict__ q, const float* __restrict__ kv,
                  const int* __restrict__ cmask, __half* __restrict__ o) {
    const int n0 = blockIdx.x * 64;
    const int h = blockIdx.y;
    const int b = blockIdx.z;
    const int tid = threadIdx.x;

    __shared__ float Qs[64][68];
    __shared__ float Ks[32][68];
    __shared__ float Vs[32][68];
    __shared__ float Ss[64][33];

    {
        const float* qbase = q + ((size_t)(b * TLc + n0)) * 1024 + h * 64;
        #pragma unroll
        for (int i = tid; i < 1024; i += 256) {
            const int r = i >> 4, c4 = (i & 15) << 2;
            *(float4*)&Qs[r][c4] = *(const float4*)(qbase + (size_t)r * 1024 + c4);
        }
    }

    const int qi = tid >> 2, dg = tid & 3;
    const int ty = tid >> 4, tx = tid & 15;
    float O[16];
    #pragma unroll
    for (int i = 0; i < 16; i++) O[i] = 0.f;
    float mval = -1e30f, lval = 0.f;

    for (int m0 = 0; m0 < Mc; m0 += 32) {
        __syncthreads();
        const float* kbase = kv + ((size_t)(b * Mc + m0)) * 2048 + h * 64;
        #pragma unroll
        for (int i = tid; i < 512; i += 256) {
            const int r = i >> 4, c4 = (i & 15) << 2;
            *(float4*)&Ks[r][c4] = *(const float4*)(kbase + (size_t)r * 2048 + c4);
            *(float4*)&Vs[r][c4] = *(const float4*)(kbase + (size_t)r * 2048 + 1024 + c4);
        }
        __syncthreads();

        float acc[4][2] = {};
        #pragma unroll
        for (int d4 = 0; d4 < 64; d4 += 4) {
            float4 b0 = *(const float4*)&Ks[tx*2+0][d4];
            float4 b1 = *(const float4*)&Ks[tx*2+1][d4];
            #pragma unroll
            for (int i = 0; i < 4; i++) {
                float4 a = *(const float4*)&Qs[ty*4+i][d4];
                acc[i][0] += a.x*b0.x + a.y*b0.y + a.z*b0.z + a.w*b0.w;
                acc[i][1] += a.x*b1.x + a.y*b1.y + a.z*b1.z + a.w*b1.w;
            }
        }
        const int msk0 = cmask[b * Mc + m0 + tx*2];
        const int msk1 = cmask[b * Mc + m0 + tx*2 + 1];
        #pragma unroll
        for (int i = 0; i < 4; i++) {
            Ss[ty*4+i][tx*2+0] = msk0 ? acc[i][0] * SCALEF : NEGF;
            Ss[ty*4+i][tx*2+1] = msk1 ? acc[i][1] * SCALEF : NEGF;
        }
        __syncthreads();

        float cmax = -1e30f;
        #pragma unroll
        for (int k = 0; k < 8; k++) cmax = fmaxf(cmax, Ss[qi][dg*8+k]);
        cmax = fmaxf(cmax, __shfl_xor_sync(0xffffffff, cmax, 1));
        cmax = fmaxf(cmax, __shfl_xor_sync(0xffffffff, cmax, 2));
        const float nm = fmaxf(mval, cmax);
        const float alpha = __expf(mval - nm);
        float psum = 0.f;
        #pragma unroll
        for (int k = 0; k < 8; k++) {
            float e = __expf(Ss[qi][dg*8+k] - nm);
            Ss[qi][dg*8+k] = e;
            psum += e;
        }
        psum += __shfl_xor_sync(0xffffffff, psum, 1);
        psum += __shfl_xor_sync(0xffffffff, psum, 2);
        lval = lval * alpha + psum;
        mval = nm;
        #pragma unroll
        for (int i = 0; i < 16; i++) O[i] *= alpha;
        __syncwarp();

        #pragma unroll
        for (int k = 0; k < 32; k++) {
            const float e = Ss[qi][k];
            float4 v0 = *(const float4*)&Vs[k][dg*16+0];
            float4 v1 = *(const float4*)&Vs[k][dg*16+4];
            float4 v2 = *(const float4*)&Vs[k][dg*16+8];
            float4 v3 = *(const float4*)&Vs[k][dg*16+12];
            O[0]  += e*v0.x; O[1]  += e*v0.y; O[2]  += e*v0.z; O[3]  += e*v0.w;
            O[4]  += e*v1.x; O[5]  += e*v1.y; O[6]  += e*v1.z; O[7]  += e*v1.w;
            O[8]  += e*v2.x; O[9]  += e*v2.y; O[10] += e*v2.z; O[11] += e*v2.w;
            O[12] += e*v3.x; O[13] += e*v3.y; O[14] += e*v3.z; O[15] += e*v3.w;
        }
    }

    const float inv = 1.0f / lval;
    const size_t off = ((size_t)(b * TLc + n0 + qi)) * 1024 + h * 64 + dg * 16;
    #pragma unroll
    for (int i = 0; i < 16; i += 2) {
        __half2 p;
        p.x = __float2half_rn(O[i] * inv);
        p.y = __float2half_rn(O[i+1] * inv);
        *(__half2*)(o + off + i) = p;
    }
}

// ---------------- temporal attention (+RoPE), fp16 out ----------------------
__global__ void __launch_bounds__(128)
temporal_attn_kernel(const float* __restrict__ qkv, const float* __restrict__ rope,
                     const int* __restrict__ amask, __half* __restrict__ ot) {
    const int l = blockIdx.x;
    const int h = blockIdx.y;
    const int b = blockIdx.z;
    const int tid = threadIdx.x;

    __shared__ float qs[16][64], ks[16][64], vs[16][64];
    __shared__ float ss[16][17];

    for (int idx = tid; idx < 1024; idx += 128) {
        const int t = idx >> 6, d = idx & 63;
        const size_t base = ((size_t)((b * Tc + t) * Lc + l)) * 1536 + h * 64 + d;
        qs[t][d] = qkv[base];
        ks[t][d] = qkv[base + 512];
        vs[t][d] = qkv[base + 1024];
    }
    __syncthreads();

    for (int idx = tid; idx < 256; idx += 128) {
        const int t = idx >> 4, r = idx & 15;
        const float p0 = rope[t * ROTc + r];
        const float p1 = rope[t * ROTc + r + 16];
        const float c0 = cosf(p0), s0 = sinf(p0);
        const float c1 = cosf(p1), s1 = sinf(p1);
        float a = qs[t][r], bb = qs[t][r + 16];
        qs[t][r]      = a * c0 - bb * s0;
        qs[t][r + 16] = bb * c1 + a * s1;
        a = ks[t][r]; bb = ks[t][r + 16];
        ks[t][r]      = a * c0 - bb * s0;
        ks[t][r + 16] = bb * c1 + a * s1;
    }
    __syncthreads();

    for (int idx = tid; idx < 256; idx += 128) {
        const int tq = idx >> 4, tk = idx & 15;
        float acc = 0.f;
        #pragma unroll
        for (int d = 0; d < 64; d++) acc += qs[tq][d] * ks[tk][d];
        ss[tq][tk] = amask[b * Tc + tk] ? acc * SCALEF : NEGF;
    }
    __syncthreads();

    if (tid < 16) {
        float mx = -1e30f;
        #pragma unroll
        for (int tk = 0; tk < 16; tk++) mx = fmaxf(mx, ss[tid][tk]);
        float sum = 0.f;
        #pragma unroll
        for (int tk = 0; tk < 16; tk++) { float e = __expf(ss[tid][tk] - mx); ss[tid][tk] = e; sum += e; }
        const float inv = 1.0f / sum;
        #pragma unroll
        for (int tk = 0; tk < 16; tk++) ss[tid][tk] *= inv;
    }
    __syncthreads();

    for (int idx = tid; idx < 1024; idx += 128) {
        const int tq = idx >> 6, d = idx & 63;
        float acc = 0.f;
        #pragma unroll
        for (int tk = 0; tk < 16; tk++) acc += ss[tq][tk] * vs[tk][d];
        const float qm = amask[b * Tc + tq] ? 1.0f : 0.0f;
        size_t off = ((size_t)((b * Tc + tq) * Lc + l)) * 512 + h * 64 + d;
        ot[off] = __float2half_rn(acc * qm);
    }
}

// ---------------- launcher ----------------
extern "C" void kernel_launch(void* const* d_in, const int* in_sizes, int n_in,
                              void* d_out, int out_size) {
    const float* x        = (const float*)d_in[0];
    const float* context  = (const float*)d_in[1];
    const float* rope     = (const float*)d_in[2];
    const float* ca_ng    = (const float*)d_in[3];
    const float* ca_nb    = (const float*)d_in[4];
    const float* ca_cng   = (const float*)d_in[5];
    const float* ca_cnb   = (const float*)d_in[6];
    const float* ca_wq    = (const float*)d_in[7];
    const float* ca_wkv   = (const float*)d_in[8];
    const float* ca_wo    = (const float*)d_in[9];
    const float* ta_ng    = (const float*)d_in[10];
    const float* ta_nb    = (const float*)d_in[11];
    const float* ta_wqkv  = (const float*)d_in[12];
    const float* ta_bqkv  = (const float*)d_in[13];
    const float* ta_wo    = (const float*)d_in[14];
    const float* ff_ng    = (const float*)d_in[15];
    const float* ff_nb    = (const float*)d_in[16];
    const float* ff_w1    = (const float*)d_in[17];
    const float* ff_w2    = (const float*)d_in[18];
    const int*   cmask    = (const int*)d_in[19];
    const int*   amask    = (const int*)d_in[20];
    float* out = (float*)d_out;

    __half *xn, *cn, *oc, *hb, *w;
    float *qb, *kvb, *qkvb, *x1, *x2;
    cudaGetSymbolAddress((void**)&xn,  g_xn);
    cudaGetSymbolAddress((void**)&cn,  g_cn);
    cudaGetSymbolAddress((void**)&oc,  g_oc);
    cudaGetSymbolAddress((void**)&hb,  g_h);
    cudaGetSymbolAddress((void**)&w,   g_w);
    cudaGetSymbolAddress((void**)&qb,  g_q);
    cudaGetSymbolAddress((void**)&kvb, g_kv);
    cudaGetSymbolAddress((void**)&qkvb, g_qkv);
    cudaGetSymbolAddress((void**)&x1,  g_x1);
    cudaGetSymbolAddress((void**)&x2,  g_x2);

    cudaFuncSetAttribute(bgemm_kernel<0,0,0,0>, cudaFuncAttributeMaxDynamicSharedMemorySize, GEMM_SMEM);
    cudaFuncSetAttribute(bgemm_kernel<0,1,0,0>, cudaFuncAttributeMaxDynamicSharedMemorySize, GEMM_SMEM);
    cudaFuncSetAttribute(bgemm_kernel<1,0,0,0>, cudaFuncAttributeMaxDynamicSharedMemorySize, GEMM_SMEM);
    cudaFuncSetAttribute(bgemm_kernel<0,0,1,1>, cudaFuncAttributeMaxDynamicSharedMemorySize, GEMM_SMEM);

    // 0) weights -> fp16
    tohalf_kernel<<<(1048576/4+255)/256, 256>>>(ca_wq,   w+WQ_OFF,   1048576);
    tohalf_kernel<<<(2097152/4+255)/256, 256>>>(ca_wkv,  w+WKV_OFF,  2097152);
    tohalf_kernel<<<(1048576/4+255)/256, 256>>>(ca_wo,   w+WO_OFF,   1048576);
    tohalf_kernel<<<(1572864/4+255)/256, 256>>>(ta_wqkv, w+WQKV_OFF, 1572864);
    tohalf_kernel<<<(524288/4+255)/256, 256>>>(ta_wo,   w+TAWO_OFF, 524288);
    tohalf_kernel<<<(4194304/4+255)/256, 256>>>(ff_w1,   w+FFW1_OFF, 4194304);
    tohalf_kernel<<<(4194304/4+255)/256, 256>>>(ff_w2,   w+FFW2_OFF, 4194304);

    // 1) xn = LN(x); cn = LN(context)
    ln_kernel<<<NR, 256>>>(x, ca_ng, ca_nb, xn);
    ln_kernel<<<Bc * Mc, 256>>>(context, ca_cng, ca_cnb, cn);

    // 2) q = xn @ ca_wq ; kv = cn @ ca_wkv
    bgemm_kernel<0,0,0,0><<<dim3(1024/128, NR/128), 256, GEMM_SMEM>>>(
        xn, w+WQ_OFF, nullptr, nullptr, qb, nullptr, 1024, 1024);
    bgemm_kernel<0,0,0,0><<<dim3(2048/128, 1024/128), 256, GEMM_SMEM>>>(
        cn, w+WKV_OFF, nullptr, nullptr, kvb, nullptr, 1024, 2048);

    // 3) cross attention -> oc (N x 1024, fp16)
    cross_attn_kernel<<<dim3(TLc/64, Hc, Bc), 256>>>(qb, kvb, cmask, oc);

    // 4) x1 = x + oc @ ca_wo
    bgemm_kernel<0,1,0,0><<<dim3(1024/128, NR/128), 256, GEMM_SMEM>>>(
        oc, w+WO_OFF, nullptr, x, x1, nullptr, 1024, 1024);

    // 5) xn2 = LN(x1); qkv = xn2 @ ta_wqkv + bias
    ln_kernel<<<NR, 256>>>(x1, ta_ng, ta_nb, xn);
    bgemm_kernel<1,0,0,0><<<dim3(1536/128, NR/128), 256, GEMM_SMEM>>>(
        xn, w+WQKV_OFF, ta_bqkv, nullptr, qkvb, nullptr, 1024, 1536);

    // 6) temporal attention -> oc reused as (N x 512, fp16)
    temporal_attn_kernel<<<dim3(Lc, HTc, Bc), 128>>>(qkvb, rope, amask, oc);

    // 7) x2 = x1 + ot @ ta_wo
    bgemm_kernel<0,1,0,0><<<dim3(1024/128, NR/128), 256, GEMM_SMEM>>>(
        oc, w+TAWO_OFF, nullptr, x1, x2, nullptr, 512, 1024);

    // 8) xn3 = LN(x2); h = gelu(xn3 @ ff_w1) fp16; out = x2 + h @ ff_w2
    ln_kernel<<<NR, 256>>>(x2, ff_ng, ff_nb, xn);
    bgemm_kernel<0,0,1,1><<<dim3(4096/128, NR/128), 256, GEMM_SMEM>>>(
        xn, w+FFW1_OFF, nullptr, nullptr, nullptr, hb, 1024, 4096);
    bgemm_kernel<0,1,0,0><<<dim3(1024/128, NR/128), 256, GEMM_SMEM>>>(
        hb, w+FFW2_OFF, nullptr, x2, out, nullptr, 4096, 1024);
}